// round 12
// baseline (speedup 1.0000x reference)
#include <cuda_runtime.h>
#include <cuda_fp16.h>
#include <cstdint>

// MultiScaleTimeMixer: fused mega-kernel, HALF batch per CTA (row-parallel),
// 3 CTAs/SM. HMMA fp16 hi/lo 3-pass, fp32 acc.

__device__ __align__(16) __half g_B0ah[16384], g_B0al[16384];
__device__ __align__(16) __half g_B0bh[16384], g_B0bl[16384];
__device__ __align__(16) __half g_B1ah[4096],  g_B1al[4096];
__device__ __align__(16) __half g_B1bh[4096],  g_B1bl[4096];
__device__ __align__(16) __half g_B2ah[1024],  g_B2al[1024];
__device__ __align__(16) __half g_B2bh[1024],  g_B2bl[1024];
__device__ __align__(16) __half g_Bc1h[128*256], g_Bc1l[128*256];
__device__ __align__(16) __half g_Bc2h[128*512], g_Bc2l[128*512];
__device__ float g_mu[2048], g_rs[2048];

__device__ __forceinline__ uint32_t smem_u32(const void* p) {
    uint32_t a;
    asm("{ .reg .u64 t; cvta.to.shared.u64 t, %1; cvt.u32.u64 %0, t; }" : "=r"(a) : "l"(p));
    return a;
}
#define LDSM4(r, addr)                                                           \
    asm volatile("ldmatrix.sync.aligned.m8n8.x4.shared.b16 {%0,%1,%2,%3}, [%4];" \
        : "=r"((r)[0]), "=r"((r)[1]), "=r"((r)[2]), "=r"((r)[3]) : "r"(addr))
#define MMA16816(d, a, b0, b1)                                                   \
    asm volatile("mma.sync.aligned.m16n8k16.row.col.f32.f16.f16.f32 "            \
        "{%0,%1,%2,%3}, {%4,%5,%6,%7}, {%8,%9}, {%0,%1,%2,%3};"                  \
        : "+f"((d)[0]), "+f"((d)[1]), "+f"((d)[2]), "+f"((d)[3])                  \
        : "r"((a)[0]), "r"((a)[1]), "r"((a)[2]), "r"((a)[3]), "r"(b0), "r"(b1))

__device__ __forceinline__ uint32_t pack2h(__half a, __half b) {
    return (uint32_t)__half_as_ushort(a) | ((uint32_t)__half_as_ushort(b) << 16);
}
__device__ __forceinline__ void hsplit(float v, __half& h, __half& l) {
    h = __float2half_rn(v); l = __float2half_rn(v - __half2float(h));
}
__device__ __forceinline__ float hswish(float v) {
    return v * fminf(fmaxf(v + 3.f, 0.f), 6.f) * (1.f / 6.f);
}
__device__ __forceinline__ void store_h(char* pH, char* pL, int idx, float v) {
    __half h, l; hsplit(v, h, l);
    *(__half*)(pH + idx * 2) = h; *(__half*)(pL + idx * 2) = l;
}
__device__ __forceinline__ void split4(char* pH, char* pL, uint32_t off, float4 v) {
    __half hx, lx, hy, ly, hz, lz, hw, lw;
    hsplit(v.x, hx, lx); hsplit(v.y, hy, ly); hsplit(v.z, hz, lz); hsplit(v.w, hw, lw);
    uint2 uh; uh.x = pack2h(hx, hy); uh.y = pack2h(hz, hw);
    uint2 ul; ul.x = pack2h(lx, ly); ul.y = pack2h(lz, lw);
    *(uint2*)(pH + off) = uh; *(uint2*)(pL + off) = ul;
}

// ---------------- LN stats (batch-global, so separate tiny kernel) ----------
__global__ void stats_k(const float* __restrict__ x) {
    int b = blockIdx.x;
    const float4* xp = (const float4*)(x + (long long)b * 16384);
    float s = 0.f, q = 0.f;
    for (int i = threadIdx.x; i < 4096; i += 256) {
        float4 v = xp[i];
        s += v.x + v.y + v.z + v.w;
        q += v.x * v.x + v.y * v.y + v.z * v.z + v.w * v.w;
    }
#pragma unroll
    for (int o = 16; o > 0; o >>= 1) {
        s += __shfl_down_sync(~0u, s, o); q += __shfl_down_sync(~0u, q, o);
    }
    __shared__ float ss[8], qs[8];
    int w = threadIdx.x >> 5, l = threadIdx.x & 31;
    if (l == 0) { ss[w] = s; qs[w] = q; }
    __syncthreads();
    if (threadIdx.x == 0) {
        float S = 0.f, Q = 0.f;
#pragma unroll
        for (int i = 0; i < 8; i++) { S += ss[i]; Q += qs[i]; }
        float mu = S * (1.f / 16384.f);
        g_mu[b] = mu;
        g_rs[b] = rsqrtf(Q * (1.f / 16384.f) - mu * mu + 1e-5f);
    }
}

__global__ void prep_k(const float* __restrict__ W0a, const float* __restrict__ W0b,
                       const float* __restrict__ W1a, const float* __restrict__ W1b,
                       const float* __restrict__ W2a, const float* __restrict__ W2b,
                       const float* __restrict__ c1w, const float* __restrict__ c2w) {
    int tid = blockIdx.x * blockDim.x + threadIdx.x, st = gridDim.x * blockDim.x;
    for (int i = tid; i < 16384; i += st) {
        int n = i >> 7, k = i & 127; float m = (k <= n) ? 1.f : 0.f;
        hsplit(m * W0a[i], g_B0ah[i], g_B0al[i]);
        hsplit(m * W0b[i], g_B0bh[i], g_B0bl[i]);
    }
    for (int i = tid; i < 4096; i += st) {
        int n = i >> 6, k = i & 63; float m = (k <= n) ? 1.f : 0.f;
        hsplit(m * W1a[i], g_B1ah[i], g_B1al[i]);
        hsplit(m * W1b[i], g_B1bh[i], g_B1bl[i]);
    }
    for (int i = tid; i < 1024; i += st) {
        int n = i >> 5, k = i & 31; float m = (k <= n) ? 1.f : 0.f;
        hsplit(m * W2a[i], g_B2ah[i], g_B2al[i]);
        hsplit(m * W2b[i], g_B2bh[i], g_B2bl[i]);
    }
    for (int i = tid; i < 128 * 256; i += st) {
        int co = i >> 8, k = i & 255;
        hsplit(c1w[co * 256 + (k & 127) * 2 + (k >> 7)], g_Bc1h[i], g_Bc1l[i]);
    }
    for (int i = tid; i < 128 * 512; i += st) {
        int co = i >> 9, k = i & 511;
        hsplit(c2w[co * 512 + (k & 127) * 4 + (k >> 7)], g_Bc2h[i], g_Bc2l[i]);
    }
}

template<int NROWS, int KCH, int SBH>
__device__ __forceinline__ void load_b(char* pBh, char* pBl,
    const __half* __restrict__ gh, const __half* __restrict__ gl,
    int ktot, int kbase, int tid) {
    constexpr int PER = KCH / 8, TOT = NROWS * PER;
    for (int i = tid; i < TOT; i += 256) {
        int n = i / PER, kq = i % PER;
        uint32_t off = (uint32_t)(n * SBH + kq * 8) * 2;
        *(uint4*)(pBh + off) = *(const uint4*)(gh + n * ktot + kbase + kq * 8);
        *(uint4*)(pBl + off) = *(const uint4*)(gl + n * ktot + kbase + kq * 8);
    }
}

// column-group for warp: MIR pairs {wcp, WC*NG-1-wcp} for tril load balance
template<int NG, int WC, bool MIR>
__device__ __forceinline__ int ggof(int g, int wcp) {
    return MIR ? (g == 0 ? wcp : (WC * NG - 1 - wcp)) : (g * WC + wcp);
}

// 3-pass MMA over KS k16-steps. A indexed by ksg = ks0+kk; B holds only the
// current chunk (stride SBH, indexed by kk). TRI: skip blocks with ksg > gg.
template<int KS, int RB, int NG, int WC, int SAH, int SBH, bool TRI, bool MIR>
__device__ __forceinline__ void mma_chunk(uint32_t uAh, uint32_t uAl,
    uint32_t uBh, uint32_t uBl, uint32_t aoff, uint32_t boff,
    int wcp, int ks0, float (*acc)[4]) {
    const int gmax = MIR ? ((WC * NG - 1 - wcp) > wcp ? (WC * NG - 1 - wcp) : wcp)
                         : ((NG - 1) * WC + wcp);
#pragma unroll
    for (int kk = 0; kk < KS; kk++) {
        int ksg = ks0 + kk;
        uint32_t ah[RB][4], al[RB][4];
        if (!TRI || ksg <= gmax) {
#pragma unroll
            for (int rb = 0; rb < RB; rb++) {
                LDSM4(ah[rb], uAh + aoff + rb * (16 * SAH * 2) + (uint32_t)ksg * 32);
                LDSM4(al[rb], uAl + aoff + rb * (16 * SAH * 2) + (uint32_t)ksg * 32);
            }
        }
#pragma unroll
        for (int g = 0; g < NG; g++) {
            int gg = ggof<NG, WC, MIR>(g, wcp);
            if (TRI && ksg > gg) continue;
            uint32_t bh[4], bl[4];
            LDSM4(bh, uBh + boff + (uint32_t)(gg * (16 * SBH * 2) + kk * 32));
            LDSM4(bl, uBl + boff + (uint32_t)(gg * (16 * SBH * 2) + kk * 32));
#pragma unroll
            for (int rb = 0; rb < RB; rb++) {
                float* a0 = acc[(rb * NG + g) * 2]; float* a1 = acc[(rb * NG + g) * 2 + 1];
                MMA16816(a0, ah[rb], bh[0], bh[1]); MMA16816(a1, ah[rb], bh[2], bh[3]);
                MMA16816(a0, al[rb], bh[0], bh[1]); MMA16816(a1, al[rb], bh[2], bh[3]);
                MMA16816(a0, ah[rb], bl[0], bl[1]); MMA16816(a1, ah[rb], bl[2], bl[3]);
            }
        }
    }
}

template<int NA> __device__ __forceinline__ void zacc(float (*acc)[4]) {
#pragma unroll
    for (int i = 0; i < NA; i++) { acc[i][0] = acc[i][1] = acc[i][2] = acc[i][3] = 0.f; }
}

template<int RB, int NG, int WC, bool HSW, bool MIR, class F>
__device__ __forceinline__ void epi(float (*acc)[4], const float* sb,
                                    int r0, int wcp, int lane, F f) {
#pragma unroll
    for (int rb = 0; rb < RB; rb++)
#pragma unroll
    for (int g = 0; g < NG; g++)
#pragma unroll
    for (int j = 0; j < 2; j++) {
        const float* a = acc[(rb * NG + g) * 2 + j];
        int cc = ggof<NG, WC, MIR>(g, wcp) * 16 + j * 8 + 2 * (lane & 3);
        int r = r0 + rb * 16 + (lane >> 2);
        float b0 = sb[cc], b1 = sb[cc + 1];
        float v0 = a[0] + b0, v1 = a[1] + b1, v2 = a[2] + b0, v3 = a[3] + b1;
        if (HSW) { v0 = hswish(v0); v1 = hswish(v1); v2 = hswish(v2); v3 = hswish(v3); }
        f(r, cc, v0); f(r, cc + 1, v1); f(r + 8, cc, v2); f(r + 8, cc + 1, v3);
    }
}

// ---------------------------------------------------------------------------
// mega kernel: one CTA = HALF batch. dsmem = 71680 B, 3 CTAs/SM.
// ---------------------------------------------------------------------------
__global__ __launch_bounds__(256, 3)
void mega_kernel(const float* __restrict__ x, const float* __restrict__ lg,
                 const float* __restrict__ lb,
                 const float* __restrict__ b0a, const float* __restrict__ b0b,
                 const float* __restrict__ c1b, const float* __restrict__ b1a,
                 const float* __restrict__ b1b,
                 const float* __restrict__ c2b, const float* __restrict__ b2a,
                 const float* __restrict__ b2b,
                 float* __restrict__ out) {
    extern __shared__ char dsm[];
    __shared__ float s_b1[128], s_b2[128], s_b3[128];
    const int tid = threadIdx.x, lane = tid & 31, wid = tid >> 5;
    const int b = blockIdx.x >> 1, half = blockIdx.x & 1;
    const uint32_t u0 = smem_u32(dsm);
    const float* xbf = x + (long long)b * 16384;
    float acc[8][4];

    const int arow = ((lane >> 3) & 1) * 8 + (lane & 7);
    const int acol8 = (lane >> 4) * 8;
    const int brow = (lane >> 4) * 8 + (lane & 7);
    const int bcol8 = ((lane >> 3) & 1) * 8;

    //======== phase 0: rows t in [half*64, half*64+64) =====================
    // A 64x136 (hi 0 / lo 17408), B 128x72 chunk (hi 34816 / lo 53248)
    {
        const int r0 = (wid & 1) * 32, wcp = wid >> 1;
        char* pAh = dsm; char* pAl = dsm + 17408;
        char* pBh = dsm + 34816; char* pBl = dsm + 53248;
        const uint32_t uAh = u0, uAl = u0 + 17408, uBh = u0 + 34816, uBl = u0 + 53248;
        const uint32_t aoff = (uint32_t)((r0 + arow) * 136 + acol8) * 2;
        const uint32_t boff = (uint32_t)(brow * 72 + bcol8) * 2;
        if (tid < 128) { s_b1[tid] = b0a[tid]; s_b2[tid] = b0b[tid]; }
        const float mu = g_mu[b], rs = g_rs[b];

        const float4* xb4 = (const float4*)(xbf + half * 8192);
#pragma unroll
        for (int qq = 0; qq < 8; qq++) {
            int q = qq * 256 + tid;
            int r = q >> 5, col = (q & 31) * 4;
            int tg = half * 64 + r;
            float4 v = xb4[q];
            float4 g = *(const float4*)(lg + tg * 128 + col);
            float4 be = *(const float4*)(lb + tg * 128 + col);
            v.x = (v.x - mu) * rs * g.x + be.x; v.y = (v.y - mu) * rs * g.y + be.y;
            v.z = (v.z - mu) * rs * g.z + be.z; v.w = (v.w - mu) * rs * g.w + be.w;
            split4(pAh, pAl, (uint32_t)(r * 136 + col) * 2, v);
        }

        // GEMM1 (tril W0a): chunk0 full B; chunk1 only rows n>=64
        zacc<8>(acc);
        load_b<128, 64, 72>(pBh, pBl, g_B0ah, g_B0al, 128, 0, tid);
        __syncthreads();
        mma_chunk<4, 2, 2, 4, 136, 72, true, true>(uAh, uAl, uBh, uBl, aoff, boff, wcp, 0, acc);
        __syncthreads();
        load_b<64, 64, 72>(pBh + 9216, pBl + 9216, g_B0ah + 8192, g_B0al + 8192, 128, 64, tid);
        __syncthreads();
        mma_chunk<4, 2, 2, 4, 136, 72, true, true>(uAh, uAl, uBh, uBl, aoff, boff, wcp, 4, acc);
        __syncthreads();
        epi<2, 2, 4, true, true>(acc, s_b1, r0, wcp, lane,
            [&](int r, int c, float v) { store_h(pAh, pAl, r * 136 + c, v); });

        // GEMM2 (tril W0b)
        zacc<8>(acc);
        load_b<128, 64, 72>(pBh, pBl, g_B0bh, g_B0bl, 128, 0, tid);
        __syncthreads();
        mma_chunk<4, 2, 2, 4, 136, 72, true, true>(uAh, uAl, uBh, uBl, aoff, boff, wcp, 0, acc);
        __syncthreads();
        load_b<64, 64, 72>(pBh + 9216, pBl + 9216, g_B0bh + 8192, g_B0bl + 8192, 128, 64, tid);
        __syncthreads();
        mma_chunk<4, 2, 2, 4, 136, 72, true, true>(uAh, uAl, uBh, uBl, aoff, boff, wcp, 4, acc);
        float* ob = out + (long long)b * 28672 + half * 64;
        epi<2, 2, 4, false, true>(acc, s_b2, r0, wcp, lane,
            [&](int r, int c, float v) { ob[c * 128 + r] = v; });
    }

    //======== phase 1: co in [half*64, half*64+64) =========================
    // conv: A 64x136 chunk (hi 0 / lo 17408), B 64x136 chunk (hi 34816 / lo 52224)
    // then: A2 64x72 (hi 0 / lo 9216), A3 (hi 18432 / lo 27648), triB (hi 36864 / lo 46080)
    {
        __syncthreads();
        const int r0c = (wid & 1) * 32, wcpc = wid >> 1;
        const int r0t = (wid & 3) * 16, wcpt = wid >> 2;     // 4 row panels x 2 col
        char* pCh = dsm;          char* pCl = dsm + 17408;
        char* pBh = dsm + 34816;  char* pBl = dsm + 52224;
        char* pA2h = dsm;         char* pA2l = dsm + 9216;
        char* pA3h = dsm + 18432; char* pA3l = dsm + 27648;
        char* pTBh = dsm + 36864; char* pTBl = dsm + 46080;
        const uint32_t uCh = u0, uCl = u0 + 17408;
        const uint32_t uBh = u0 + 34816, uBl = u0 + 52224;
        const uint32_t uA2h = u0, uA2l = u0 + 9216;
        const uint32_t uA3h = u0 + 18432, uA3l = u0 + 27648;
        const uint32_t uTBh = u0 + 36864, uTBl = u0 + 46080;
        const uint32_t aoffc = (uint32_t)((r0c + arow) * 136 + acol8) * 2;
        const uint32_t boffc = (uint32_t)(brow * 136 + bcol8) * 2;
        const uint32_t aofft = (uint32_t)((r0t + arow) * 72 + acol8) * 2;
        const uint32_t bofft = (uint32_t)(brow * 72 + bcol8) * 2;
        if (tid < 64) {
            s_b1[tid] = c1b[half * 64 + tid];
            s_b2[tid] = b1a[tid]; s_b3[tid] = b1b[tid];
        }

        zacc<4>(acc);
#pragma unroll 1
        for (int ch = 0; ch < 2; ch++) {
#pragma unroll
            for (int qq = 0; qq < 8; qq++) {
                int q = qq * 256 + tid;
                int r = q >> 5, col = (q & 31) * 4;
                float4 v = *(const float4*)(xbf + r * 256 + ch * 128 + col);
                split4(pCh, pCl, (uint32_t)(r * 136 + col) * 2, v);
            }
            load_b<64, 128, 136>(pBh, pBl, g_Bc1h + half * 64 * 256,
                                 g_Bc1l + half * 64 * 256, 256, ch * 128, tid);
            __syncthreads();
            mma_chunk<8, 2, 1, 4, 136, 136, false, false>(uCh, uCl, uBh, uBl,
                aoffc, boffc, wcpc, 0, acc);    // both chunk-local: ks0 = 0
            __syncthreads();
        }
        // conv + bias -> A2 (row = co_local, col = s)
        epi<2, 1, 4, false, false>(acc, s_b1, r0c, wcpc, lane,
            [&](int r, int c, float v) { store_h(pA2h, pA2l, c * 72 + r, v); });

        // triu1a (tril W1a) + hsw -> A3
        zacc<4>(acc);
        load_b<64, 64, 72>(pTBh, pTBl, g_B1ah, g_B1al, 64, 0, tid);
        __syncthreads();
        mma_chunk<4, 1, 2, 2, 72, 72, true, true>(uA2h, uA2l, uTBh, uTBl,
            aofft, bofft, wcpt, 0, acc);
        __syncthreads();
        epi<1, 2, 2, true, true>(acc, s_b2, r0t, wcpt, lane,
            [&](int r, int c, float v) { store_h(pA3h, pA3l, r * 72 + c, v); });

        // triu1b (tril W1b) -> out[b, 128+j, co]
        zacc<4>(acc);
        load_b<64, 64, 72>(pTBh, pTBl, g_B1bh, g_B1bl, 64, 0, tid);
        __syncthreads();
        mma_chunk<4, 1, 2, 2, 72, 72, true, true>(uA3h, uA3l, uTBh, uTBl,
            aofft, bofft, wcpt, 0, acc);
        float* ob = out + (long long)b * 28672 + 16384 + half * 64;
        epi<1, 2, 2, false, true>(acc, s_b3, r0t, wcpt, lane,
            [&](int r, int c, float v) { ob[c * 128 + r] = v; });
    }

    //======== phase 2: co in [half*64, half*64+64) =========================
    // conv: A 32x136 chunk (hi 0 / lo 8704), B 64x136 chunk (hi 17408 / lo 34816)
    // then: A2 64x40 (hi 0 / lo 5120), A3 (hi 10240 / lo 15360), triB (hi 20480 / lo 23040)
    {
        __syncthreads();
        const int r0c = (wid & 1) * 16, wcpc = wid >> 1;     // M=32: 2 panels x 4 col
        const int r0t = (wid & 3) * 16, wcpt = wid >> 2;     // M=64: 4 panels x 2 col
        char* pCh = dsm;          char* pCl = dsm + 8704;
        char* pBh = dsm + 17408;  char* pBl = dsm + 34816;
        char* pA2h = dsm;         char* pA2l = dsm + 5120;
        char* pA3h = dsm + 10240; char* pA3l = dsm + 15360;
        char* pTBh = dsm + 20480; char* pTBl = dsm + 23040;
        const uint32_t uCh = u0, uCl = u0 + 8704;
        const uint32_t uBh = u0 + 17408, uBl = u0 + 34816;
        const uint32_t uA2h = u0, uA2l = u0 + 5120;
        const uint32_t uA3h = u0 + 10240, uA3l = u0 + 15360;
        const uint32_t uTBh = u0 + 20480, uTBl = u0 + 23040;
        const uint32_t aoffc = (uint32_t)((r0c + arow) * 136 + acol8) * 2;
        const uint32_t boffc = (uint32_t)(brow * 136 + bcol8) * 2;
        const uint32_t aofft = (uint32_t)((r0t + arow) * 40 + acol8) * 2;
        const uint32_t bofft = (uint32_t)(brow * 40 + bcol8) * 2;
        if (tid < 64) s_b1[tid] = c2b[half * 64 + tid];
        if (tid < 32) { s_b2[tid] = b2a[tid]; s_b3[tid] = b2b[tid]; }

        zacc<2>(acc);
#pragma unroll 1
        for (int ch = 0; ch < 4; ch++) {
#pragma unroll
            for (int qq = 0; qq < 4; qq++) {
                int q = qq * 256 + tid;
                int r = q >> 5, col = (q & 31) * 4;
                float4 v = *(const float4*)(xbf + r * 512 + ch * 128 + col);
                split4(pCh, pCl, (uint32_t)(r * 136 + col) * 2, v);
            }
            load_b<64, 128, 136>(pBh, pBl, g_Bc2h + half * 64 * 512,
                                 g_Bc2l + half * 64 * 512, 512, ch * 128, tid);
            __syncthreads();
            mma_chunk<8, 1, 1, 4, 136, 136, false, false>(uCh, uCl, uBh, uBl,
                aoffc, boffc, wcpc, 0, acc);    // both chunk-local: ks0 = 0
            __syncthreads();
        }
        epi<1, 1, 4, false, false>(acc, s_b1, r0c, wcpc, lane,
            [&](int r, int c, float v) { store_h(pA2h, pA2l, c * 40 + r, v); });

        zacc<2>(acc);
        load_b<32, 32, 40>(pTBh, pTBl, g_B2ah, g_B2al, 32, 0, tid);
        __syncthreads();
        mma_chunk<2, 1, 1, 2, 40, 40, true, false>(uA2h, uA2l, uTBh, uTBl,
            aofft, bofft, wcpt, 0, acc);
        __syncthreads();
        epi<1, 1, 2, true, false>(acc, s_b2, r0t, wcpt, lane,
            [&](int r, int c, float v) { store_h(pA3h, pA3l, r * 40 + c, v); });

        zacc<2>(acc);
        load_b<32, 32, 40>(pTBh, pTBl, g_B2bh, g_B2bl, 32, 0, tid);
        __syncthreads();
        mma_chunk<2, 1, 1, 2, 40, 40, true, false>(uA3h, uA3l, uTBh, uTBl,
            aofft, bofft, wcpt, 0, acc);
        float* ob = out + (long long)b * 28672 + 24576 + half * 64;
        epi<1, 1, 2, false, false>(acc, s_b3, r0t, wcpt, lane,
            [&](int r, int c, float v) { ob[c * 128 + r] = v; });
    }
}

// ---------------------------------------------------------------------------
extern "C" void kernel_launch(void* const* d_in, const int* in_sizes, int n_in,
                              void* d_out, int out_size) {
    const float* x   = (const float*)d_in[0];
    const float* lg  = (const float*)d_in[1];
    const float* lb  = (const float*)d_in[2];
    const float* W0a = (const float*)d_in[3];
    const float* b0a = (const float*)d_in[4];
    const float* W0b = (const float*)d_in[5];
    const float* b0b = (const float*)d_in[6];
    const float* c1w = (const float*)d_in[7];
    const float* c1b = (const float*)d_in[8];
    const float* W1a = (const float*)d_in[9];
    const float* b1a = (const float*)d_in[10];
    const float* W1b = (const float*)d_in[11];
    const float* b1b = (const float*)d_in[12];
    const float* c2w = (const float*)d_in[13];
    const float* c2b = (const float*)d_in[14];
    const float* W2a = (const float*)d_in[15];
    const float* b2a = (const float*)d_in[16];
    const float* W2b = (const float*)d_in[17];
    const float* b2b = (const float*)d_in[18];
    float* out = (float*)d_out;

    const int ds = 71680;
    cudaFuncSetAttribute(mega_kernel, cudaFuncAttributeMaxDynamicSharedMemorySize, ds);

    stats_k<<<2048, 256>>>(x);
    prep_k<<<128, 256>>>(W0a, W0b, W1a, W1b, W2a, W2b, c1w, c2w);
    mega_kernel<<<4096, 256, ds>>>(x, lg, lb, b0a, b0b, c1b, b1a, b1b,
                                   c2b, b2a, b2b, out);
}

// round 13
// speedup vs baseline: 1.0807x; 1.0807x over previous
#include <cuda_runtime.h>
#include <cuda_fp16.h>
#include <cstdint>

// MultiScaleTimeMixer: fused mega-kernel (1 batch/CTA, 3 phases), cp.async
// double-buffered B chunks (K=32). HMMA fp16 hi/lo 3-pass, fp32 acc.

__device__ __align__(16) __half g_B0ah[16384], g_B0al[16384];
__device__ __align__(16) __half g_B0bh[16384], g_B0bl[16384];
__device__ __align__(16) __half g_B1ah[4096],  g_B1al[4096];
__device__ __align__(16) __half g_B1bh[4096],  g_B1bl[4096];
__device__ __align__(16) __half g_B2ah[1024],  g_B2al[1024];
__device__ __align__(16) __half g_B2bh[1024],  g_B2bl[1024];
__device__ __align__(16) __half g_Bc1h[128*256], g_Bc1l[128*256];
__device__ __align__(16) __half g_Bc2h[128*512], g_Bc2l[128*512];

__device__ __forceinline__ uint32_t smem_u32(const void* p) {
    uint32_t a;
    asm("{ .reg .u64 t; cvta.to.shared.u64 t, %1; cvt.u32.u64 %0, t; }" : "=r"(a) : "l"(p));
    return a;
}
#define LDSM4(r, addr)                                                           \
    asm volatile("ldmatrix.sync.aligned.m8n8.x4.shared.b16 {%0,%1,%2,%3}, [%4];" \
        : "=r"((r)[0]), "=r"((r)[1]), "=r"((r)[2]), "=r"((r)[3]) : "r"(addr))
#define MMA16816(d, a, b0, b1)                                                   \
    asm volatile("mma.sync.aligned.m16n8k16.row.col.f32.f16.f16.f32 "            \
        "{%0,%1,%2,%3}, {%4,%5,%6,%7}, {%8,%9}, {%0,%1,%2,%3};"                  \
        : "+f"((d)[0]), "+f"((d)[1]), "+f"((d)[2]), "+f"((d)[3])                  \
        : "r"((a)[0]), "r"((a)[1]), "r"((a)[2]), "r"((a)[3]), "r"(b0), "r"(b1))
#define CP16(sa, g)                                                              \
    asm volatile("cp.async.cg.shared.global [%0], [%1], 16;" :: "r"(sa), "l"(g))
#define CP_COMMIT() asm volatile("cp.async.commit_group;" ::: "memory")
#define CP_WAIT1()  asm volatile("cp.async.wait_group 1;" ::: "memory")
#define CP_WAIT0()  asm volatile("cp.async.wait_group 0;" ::: "memory")

__device__ __forceinline__ uint32_t pack2h(__half a, __half b) {
    return (uint32_t)__half_as_ushort(a) | ((uint32_t)__half_as_ushort(b) << 16);
}
__device__ __forceinline__ void hsplit(float v, __half& h, __half& l) {
    h = __float2half_rn(v); l = __float2half_rn(v - __half2float(h));
}
__device__ __forceinline__ float hswish(float v) {
    return v * fminf(fmaxf(v + 3.f, 0.f), 6.f) * (1.f / 6.f);
}
__device__ __forceinline__ void store_h(char* pH, char* pL, int idx, float v) {
    __half h, l; hsplit(v, h, l);
    *(__half*)(pH + idx * 2) = h; *(__half*)(pL + idx * 2) = l;
}
__device__ __forceinline__ void split4(char* pH, char* pL, uint32_t off, float4 v) {
    __half hx, lx, hy, ly, hz, lz, hw, lw;
    hsplit(v.x, hx, lx); hsplit(v.y, hy, ly); hsplit(v.z, hz, lz); hsplit(v.w, hw, lw);
    uint2 uh; uh.x = pack2h(hx, hy); uh.y = pack2h(hz, hw);
    uint2 ul; ul.x = pack2h(lx, ly); ul.y = pack2h(lz, lw);
    *(uint2*)(pH + off) = uh; *(uint2*)(pL + off) = ul;
}

__global__ void prep_k(const float* __restrict__ W0a, const float* __restrict__ W0b,
                       const float* __restrict__ W1a, const float* __restrict__ W1b,
                       const float* __restrict__ W2a, const float* __restrict__ W2b,
                       const float* __restrict__ c1w, const float* __restrict__ c2w) {
    int tid = blockIdx.x * blockDim.x + threadIdx.x, st = gridDim.x * blockDim.x;
    for (int i = tid; i < 16384; i += st) {
        int n = i >> 7, k = i & 127; float m = (k <= n) ? 1.f : 0.f;
        hsplit(m * W0a[i], g_B0ah[i], g_B0al[i]);
        hsplit(m * W0b[i], g_B0bh[i], g_B0bl[i]);
    }
    for (int i = tid; i < 4096; i += st) {
        int n = i >> 6, k = i & 63; float m = (k <= n) ? 1.f : 0.f;
        hsplit(m * W1a[i], g_B1ah[i], g_B1al[i]);
        hsplit(m * W1b[i], g_B1bh[i], g_B1bl[i]);
    }
    for (int i = tid; i < 1024; i += st) {
        int n = i >> 5, k = i & 31; float m = (k <= n) ? 1.f : 0.f;
        hsplit(m * W2a[i], g_B2ah[i], g_B2al[i]);
        hsplit(m * W2b[i], g_B2bh[i], g_B2bl[i]);
    }
    for (int i = tid; i < 128 * 256; i += st) {
        int co = i >> 8, k = i & 255;
        hsplit(c1w[co * 256 + (k & 127) * 2 + (k >> 7)], g_Bc1h[i], g_Bc1l[i]);
    }
    for (int i = tid; i < 128 * 512; i += st) {
        int co = i >> 9, k = i & 511;
        hsplit(c2w[co * 512 + (k & 127) * 4 + (k >> 7)], g_Bc2h[i], g_Bc2l[i]);
    }
}

// sync-load a B tile (used for small single-chunk triu GEMMs)
template<int NROWS, int KCH, int SBH>
__device__ __forceinline__ void load_b(char* pBh, char* pBl,
    const __half* __restrict__ gh, const __half* __restrict__ gl,
    int ktot, int kbase, int tid) {
    constexpr int PER = KCH / 8, TOT = NROWS * PER;
    for (int i = tid; i < TOT; i += 256) {
        int n = i / PER, kq = i % PER;
        uint32_t off = (uint32_t)(n * SBH + kq * 8) * 2;
        *(uint4*)(pBh + off) = *(const uint4*)(gh + n * ktot + kbase + kq * 8);
        *(uint4*)(pBl + off) = *(const uint4*)(gl + n * ktot + kbase + kq * 8);
    }
}

// async-load one K=32 B chunk (stride 40 halves = 80B, 16B-aligned rows).
// rows n < nmin skipped (tril zeros — mma skips those blocks too).
template<int NROWS>
__device__ __forceinline__ void cpb32(uint32_t sh, uint32_t sl,
    const __half* __restrict__ gh, const __half* __restrict__ gl,
    int ktot, int kbase, int nmin, int tid) {
    constexpr int TOT = NROWS * 4;
    for (int i = tid; i < TOT; i += 256) {
        int n = i >> 2, kq = i & 3;
        if (n < nmin) continue;
        uint32_t off = (uint32_t)(n * 40 + kq * 8) * 2;
        const __half* gp = gh + n * ktot + kbase + kq * 8;
        CP16(sh + off, gp);
        CP16(sl + off, gl + (gp - gh));
    }
}

// 3-pass MMA over KS k16-steps. A indexed by ksg = ks0+kk; B chunk-local
// (stride SBH, indexed by kk). TRI: skip blocks with ksg > gg = g*WC+wcp.
template<int KS, int RB, int NG, int WC, int SAH, int SBH, bool TRI>
__device__ __forceinline__ void mma_chunk(uint32_t uAh, uint32_t uAl,
    uint32_t uBh, uint32_t uBl, uint32_t aoff, uint32_t boff,
    int wcp, int ks0, float (*acc)[4]) {
#pragma unroll
    for (int kk = 0; kk < KS; kk++) {
        int ksg = ks0 + kk;
        uint32_t ah[RB][4], al[RB][4];
        if (!TRI || ksg <= (NG - 1) * WC + wcp) {
#pragma unroll
            for (int rb = 0; rb < RB; rb++) {
                LDSM4(ah[rb], uAh + aoff + rb * (16 * SAH * 2) + (uint32_t)ksg * 32);
                LDSM4(al[rb], uAl + aoff + rb * (16 * SAH * 2) + (uint32_t)ksg * 32);
            }
        }
#pragma unroll
        for (int g = 0; g < NG; g++) {
            int gg = g * WC + wcp;
            if (TRI && ksg > gg) continue;
            uint32_t bh[4], bl[4];
            LDSM4(bh, uBh + boff + (uint32_t)(gg * (16 * SBH * 2) + kk * 32));
            LDSM4(bl, uBl + boff + (uint32_t)(gg * (16 * SBH * 2) + kk * 32));
#pragma unroll
            for (int rb = 0; rb < RB; rb++) {
                float* a0 = acc[(rb * NG + g) * 2]; float* a1 = acc[(rb * NG + g) * 2 + 1];
                MMA16816(a0, ah[rb], bh[0], bh[1]); MMA16816(a1, ah[rb], bh[2], bh[3]);
                MMA16816(a0, al[rb], bh[0], bh[1]); MMA16816(a1, al[rb], bh[2], bh[3]);
                MMA16816(a0, ah[rb], bl[0], bl[1]); MMA16816(a1, ah[rb], bl[2], bl[3]);
            }
        }
    }
}

// pipelined GEMM: NC chunks of K=32, double-buffered B via cp.async.
// A is K-resident (ks0 = c*2). TRI additionally prunes B rows per chunk.
template<int NC, int RB, int NG, int WC, int SAH, bool TRI>
__device__ __forceinline__ void pipe_gemm(uint32_t uAh, uint32_t uAl,
    uint32_t b0h, uint32_t b0l, uint32_t b1h, uint32_t b1l,
    const __half* __restrict__ gh, const __half* __restrict__ gl, int ktot,
    uint32_t aoff, uint32_t boff, int wcp, int tid, float (*acc)[4]) {
    cpb32<128>(b0h, b0l, gh, gl, ktot, 0, 0, tid);
    CP_COMMIT();
#pragma unroll 1
    for (int c = 0; c < NC; c++) {
        if (c + 1 < NC) {
            uint32_t nh = ((c + 1) & 1) ? b1h : b0h;
            uint32_t nl = ((c + 1) & 1) ? b1l : b0l;
            cpb32<128>(nh, nl, gh, gl, ktot, (c + 1) * 32, TRI ? (c + 1) * 32 : 0, tid);
            CP_COMMIT();
            CP_WAIT1();
        } else {
            CP_WAIT0();
        }
        __syncthreads();
        uint32_t bh = (c & 1) ? b1h : b0h;
        uint32_t bl = (c & 1) ? b1l : b0l;
        mma_chunk<2, RB, NG, WC, SAH, 40, TRI>(uAh, uAl, bh, bl, aoff, boff, wcp,
                                               c * 2, acc);
        __syncthreads();
    }
}

template<int NA> __device__ __forceinline__ void zacc(float (*acc)[4]) {
#pragma unroll
    for (int i = 0; i < NA; i++) { acc[i][0] = acc[i][1] = acc[i][2] = acc[i][3] = 0.f; }
}

template<int RB, int NG, int WC, bool HSW, class F>
__device__ __forceinline__ void epi(float (*acc)[4], const float* sb,
                                    int r0, int wcp, int lane, F f) {
#pragma unroll
    for (int rb = 0; rb < RB; rb++)
#pragma unroll
    for (int g = 0; g < NG; g++)
#pragma unroll
    for (int j = 0; j < 2; j++) {
        const float* a = acc[(rb * NG + g) * 2 + j];
        int cc = (g * WC + wcp) * 16 + j * 8 + 2 * (lane & 3);
        int r = r0 + rb * 16 + (lane >> 2);
        float b0 = sb[cc], b1 = sb[cc + 1];
        float v0 = a[0] + b0, v1 = a[1] + b1, v2 = a[2] + b0, v3 = a[3] + b1;
        if (HSW) { v0 = hswish(v0); v1 = hswish(v1); v2 = hswish(v2); v3 = hswish(v3); }
        f(r, cc, v0); f(r, cc + 1, v1); f(r + 8, cc, v2); f(r + 8, cc + 1, v3);
    }
}

// ---------------------------------------------------------------------------
// mega kernel: one CTA = one batch. dsmem = 110592 B, 2 CTAs/SM.
// ---------------------------------------------------------------------------
__global__ __launch_bounds__(256, 2)
void mega_kernel(const float* __restrict__ x, const float* __restrict__ lg,
                 const float* __restrict__ lb,
                 const float* __restrict__ b0a, const float* __restrict__ b0b,
                 const float* __restrict__ c1b, const float* __restrict__ b1a,
                 const float* __restrict__ b1b,
                 const float* __restrict__ c2b, const float* __restrict__ b2a,
                 const float* __restrict__ b2b,
                 float* __restrict__ out) {
    extern __shared__ char dsm[];
    __shared__ float s_s[8], s_q[8], s_ms[2], s_b1[128], s_b2[128], s_b3[128];
    const int tid = threadIdx.x, lane = tid & 31, wid = tid >> 5;
    const int b = blockIdx.x;
    const uint32_t u0 = smem_u32(dsm);
    const float* xbf = x + (long long)b * 16384;
    float acc[16][4];

    const int arow = ((lane >> 3) & 1) * 8 + (lane & 7);
    const int acol8 = (lane >> 4) * 8;
    const int brow = (lane >> 4) * 8 + (lane & 7);
    const int bcol8 = ((lane >> 3) & 1) * 8;
    const uint32_t boff40 = (uint32_t)(brow * 40 + bcol8) * 2;

    //======================= phase 0: scale 0 ==============================
    // A 128x136 (hi 0 / lo 34816); B bufs: b0 hi 69632 / lo 79872,
    // b1 hi 90112 / lo 100352 (each 10240 = 128x40x2). Total 110592.
    {
        const int wcp = wid >> 2, r0 = (wid & 3) * 32;
        char* pAh = dsm; char* pAl = dsm + 34816;
        const uint32_t uAh = u0, uAl = u0 + 34816;
        const uint32_t b0h = u0 + 69632, b0l = u0 + 79872;
        const uint32_t b1h = u0 + 90112, b1l = u0 + 100352;
        const uint32_t aoff = (uint32_t)((r0 + arow) * 136 + acol8) * 2;
        if (tid < 128) { s_b1[tid] = b0a[tid]; s_b2[tid] = b0b[tid]; }

        const float4* xb = (const float4*)xbf;
        float sm = 0.f, sq = 0.f;
#pragma unroll
        for (int q = 0; q < 16; q++) {
            float4 v = xb[q * 256 + tid];
            sm += v.x + v.y + v.z + v.w;
            sq += v.x * v.x + v.y * v.y + v.z * v.z + v.w * v.w;
        }
#pragma unroll
        for (int o = 16; o > 0; o >>= 1) {
            sm += __shfl_down_sync(~0u, sm, o); sq += __shfl_down_sync(~0u, sq, o);
        }
        if (lane == 0) { s_s[wid] = sm; s_q[wid] = sq; }
        __syncthreads();
        if (tid == 0) {
            float S = 0.f, Q = 0.f;
#pragma unroll
            for (int i = 0; i < 8; i++) { S += s_s[i]; Q += s_q[i]; }
            float mu = S * (1.f / 16384.f);
            s_ms[0] = mu; s_ms[1] = rsqrtf(Q * (1.f / 16384.f) - mu * mu + 1e-5f);
        }
        __syncthreads();
        const float mu = s_ms[0], rs = s_ms[1];
#pragma unroll
        for (int qq = 0; qq < 16; qq++) {
            int q = qq * 256 + tid;
            int r = q >> 5, col = (q & 31) * 4;
            float4 v = xb[q];
            float4 g = *(const float4*)(lg + r * 128 + col);
            float4 be = *(const float4*)(lb + r * 128 + col);
            v.x = (v.x - mu) * rs * g.x + be.x; v.y = (v.y - mu) * rs * g.y + be.y;
            v.z = (v.z - mu) * rs * g.z + be.z; v.w = (v.w - mu) * rs * g.w + be.w;
            split4(pAh, pAl, (uint32_t)(r * 136 + col) * 2, v);
        }

        zacc<16>(acc);
        pipe_gemm<4, 2, 4, 2, 136, true>(uAh, uAl, b0h, b0l, b1h, b1l,
            g_B0ah, g_B0al, 128, aoff, boff40, wcp, tid, acc);
        epi<2, 4, 2, true>(acc, s_b1, r0, wcp, lane,
            [&](int r, int c, float v) { store_h(pAh, pAl, r * 136 + c, v); });

        zacc<16>(acc);
        pipe_gemm<4, 2, 4, 2, 136, true>(uAh, uAl, b0h, b0l, b1h, b1l,
            g_B0bh, g_B0bl, 128, aoff, boff40, wcp, tid, acc);
        float* ob = out + (long long)b * 28672;
        epi<2, 4, 2, false>(acc, s_b2, r0, wcp, lane,
            [&](int r, int c, float v) { ob[c * 128 + r] = v; });
    }

    //======================= phase 1: scale 1 ==============================
    // conv A 64x264 (hi 0 / lo 33792); B bufs: b0 hi 67584 / lo 77824,
    // b1 hi 88064 / lo 98304 (end 108544).
    // post-conv: A2 hi 0 / lo 18432; A3 hi 36864 / lo 55296; triB hi 88064 /
    // lo 97280 (aliases dead b1).
    {
        __syncthreads();
        const int r0c = (wid & 1) * 32, wcpc = wid >> 1;
        const int r0t = (wid & 3) * 32, wcpt = wid >> 2;
        char* pCh = dsm;          char* pCl = dsm + 33792;
        char* pA2h = dsm;         char* pA2l = dsm + 18432;
        char* pA3h = dsm + 36864; char* pA3l = dsm + 55296;
        char* pTBh = dsm + 88064; char* pTBl = dsm + 97280;
        const uint32_t uCh = u0, uCl = u0 + 33792;
        const uint32_t b0h = u0 + 67584, b0l = u0 + 77824;
        const uint32_t b1h = u0 + 88064, b1l = u0 + 98304;
        const uint32_t uA2h = u0, uA2l = u0 + 18432;
        const uint32_t uA3h = u0 + 36864, uA3l = u0 + 55296;
        const uint32_t uTBh = u0 + 88064, uTBl = u0 + 97280;
        const uint32_t aoffc = (uint32_t)((r0c + arow) * 264 + acol8) * 2;
        const uint32_t aofft = (uint32_t)((r0t + arow) * 72 + acol8) * 2;
        const uint32_t bofft = (uint32_t)(brow * 72 + bcol8) * 2;
        if (tid < 128) s_b1[tid] = c1b[tid];
        if (tid < 64) { s_b2[tid] = b1a[tid]; s_b3[tid] = b1b[tid]; }

        const float4* xb = (const float4*)xbf;
#pragma unroll
        for (int qq = 0; qq < 16; qq++) {
            int q = qq * 256 + tid;
            int r = q >> 6, col = (q & 63) * 4;
            split4(pCh, pCl, (uint32_t)(r * 264 + col) * 2, xb[q]);
        }

        zacc<8>(acc);
        pipe_gemm<8, 2, 2, 4, 264, false>(uCh, uCl, b0h, b0l, b1h, b1l,
            g_Bc1h, g_Bc1l, 256, aoffc, boff40, wcpc, tid, acc);
        epi<2, 2, 4, false>(acc, s_b1, r0c, wcpc, lane,
            [&](int r, int c, float v) { store_h(pA2h, pA2l, c * 72 + r, v); });

        zacc<8>(acc);
        load_b<64, 64, 72>(pTBh, pTBl, g_B1ah, g_B1al, 64, 0, tid);
        __syncthreads();
        mma_chunk<4, 2, 2, 2, 72, 72, true>(uA2h, uA2l, uTBh, uTBl, aofft, bofft, wcpt, 0, acc);
        __syncthreads();
        epi<2, 2, 2, true>(acc, s_b2, r0t, wcpt, lane,
            [&](int r, int c, float v) { store_h(pA3h, pA3l, r * 72 + c, v); });

        zacc<8>(acc);
        load_b<64, 64, 72>(pTBh, pTBl, g_B1bh, g_B1bl, 64, 0, tid);
        __syncthreads();
        mma_chunk<4, 2, 2, 2, 72, 72, true>(uA3h, uA3l, uTBh, uTBl, aofft, bofft, wcpt, 0, acc);
        float* ob = out + (long long)b * 28672 + 16384;
        epi<2, 2, 2, false>(acc, s_b3, r0t, wcpt, lane,
            [&](int r, int c, float v) { ob[c * 128 + r] = v; });
    }

    //======================= phase 2: scale 2 ==============================
    // conv A 32x520 (hi 0 / lo 33280); B bufs: b0 hi 66560 / lo 76800,
    // b1 hi 87040 / lo 97280 (end 107520).
    // post-conv: A2 hi 0 / lo 10240; A3 hi 20480 / lo 30720; triB hi 40960 /
    // lo 43520 (all alias dead conv-A region).
    {
        __syncthreads();
        const int r0c = (wid & 1) * 16, wcpc = wid >> 1;
        const int r0t = wid * 16;
        char* pFAh = dsm;          char* pFAl = dsm + 33280;
        char* pA2h = dsm;          char* pA2l = dsm + 10240;
        char* pA3h = dsm + 20480;  char* pA3l = dsm + 30720;
        char* pTBh = dsm + 40960;  char* pTBl = dsm + 43520;
        const uint32_t uFAh = u0, uFAl = u0 + 33280;
        const uint32_t b0h = u0 + 66560, b0l = u0 + 76800;
        const uint32_t b1h = u0 + 87040, b1l = u0 + 97280;
        const uint32_t uA2h = u0, uA2l = u0 + 10240;
        const uint32_t uA3h = u0 + 20480, uA3l = u0 + 30720;
        const uint32_t uTBh = u0 + 40960, uTBl = u0 + 43520;
        const uint32_t aoffc = (uint32_t)((r0c + arow) * 520 + acol8) * 2;
        const uint32_t aofft = (uint32_t)((r0t + arow) * 40 + acol8) * 2;
        const uint32_t bofft = (uint32_t)(brow * 40 + bcol8) * 2;
        if (tid < 128) s_b1[tid] = c2b[tid];
        if (tid < 32) { s_b2[tid] = b2a[tid]; s_b3[tid] = b2b[tid]; }

#pragma unroll
        for (int qq = 0; qq < 16; qq++) {
            int q = qq * 256 + tid;
            int r = q >> 7, col4 = (q & 127) * 4;
            float4 v = *(const float4*)(xbf + r * 512 + col4);
            split4(pFAh, pFAl, (uint32_t)(r * 520 + col4) * 2, v);
        }

        zacc<4>(acc);
        pipe_gemm<16, 1, 2, 4, 520, false>(uFAh, uFAl, b0h, b0l, b1h, b1l,
            g_Bc2h, g_Bc2l, 512, aoffc, boff40, wcpc, tid, acc);
        epi<1, 2, 4, false>(acc, s_b1, r0c, wcpc, lane,
            [&](int r, int c, float v) { store_h(pA2h, pA2l, c * 40 + r, v); });

        zacc<4>(acc);
        load_b<32, 32, 40>(pTBh, pTBl, g_B2ah, g_B2al, 32, 0, tid);
        __syncthreads();
        mma_chunk<2, 1, 2, 1, 40, 40, true>(uA2h, uA2l, uTBh, uTBl, aofft, bofft, 0, 0, acc);
        __syncthreads();
        epi<1, 2, 1, true>(acc, s_b2, r0t, 0, lane,
            [&](int r, int c, float v) { store_h(pA3h, pA3l, r * 40 + c, v); });

        zacc<4>(acc);
        load_b<32, 32, 40>(pTBh, pTBl, g_B2bh, g_B2bl, 32, 0, tid);
        __syncthreads();
        mma_chunk<2, 1, 2, 1, 40, 40, true>(uA3h, uA3l, uTBh, uTBl, aofft, bofft, 0, 0, acc);
        float* ob = out + (long long)b * 28672 + 24576;
        epi<1, 2, 1, false>(acc, s_b3, r0t, 0, lane,
            [&](int r, int c, float v) { ob[c * 128 + r] = v; });
    }
}

// ---------------------------------------------------------------------------
extern "C" void kernel_launch(void* const* d_in, const int* in_sizes, int n_in,
                              void* d_out, int out_size) {
    const float* x   = (const float*)d_in[0];
    const float* lg  = (const float*)d_in[1];
    const float* lb  = (const float*)d_in[2];
    const float* W0a = (const float*)d_in[3];
    const float* b0a = (const float*)d_in[4];
    const float* W0b = (const float*)d_in[5];
    const float* b0b = (const float*)d_in[6];
    const float* c1w = (const float*)d_in[7];
    const float* c1b = (const float*)d_in[8];
    const float* W1a = (const float*)d_in[9];
    const float* b1a = (const float*)d_in[10];
    const float* W1b = (const float*)d_in[11];
    const float* b1b = (const float*)d_in[12];
    const float* c2w = (const float*)d_in[13];
    const float* c2b = (const float*)d_in[14];
    const float* W2a = (const float*)d_in[15];
    const float* b2a = (const float*)d_in[16];
    const float* W2b = (const float*)d_in[17];
    const float* b2b = (const float*)d_in[18];
    float* out = (float*)d_out;

    const int ds = 110592;
    cudaFuncSetAttribute(mega_kernel, cudaFuncAttributeMaxDynamicSharedMemorySize, ds);

    prep_k<<<128, 256>>>(W0a, W0b, W1a, W1b, W2a, W2b, c1w, c2w);
    mega_kernel<<<2048, 256, ds>>>(x, lg, lb, b0a, b0b, c1b, b1a, b1b,
                                   c2b, b2a, b2b, out);
}

// round 14
// speedup vs baseline: 1.3302x; 1.2309x over previous
#include <cuda_runtime.h>
#include <cuda_fp16.h>
#include <cstdint>

// MultiScaleTimeMixer: fused mega-kernel (1 batch/CTA, 3 phases).
// 2-pass mixed precision: A single fp16, weights fp16 hi/lo, fp32 acc.
// 3 CTAs/SM (74752 B dsmem, 80-reg cap).

__device__ __align__(16) __half g_B0ah[16384], g_B0al[16384];
__device__ __align__(16) __half g_B0bh[16384], g_B0bl[16384];
__device__ __align__(16) __half g_B1ah[4096],  g_B1al[4096];
__device__ __align__(16) __half g_B1bh[4096],  g_B1bl[4096];
__device__ __align__(16) __half g_B2ah[1024],  g_B2al[1024];
__device__ __align__(16) __half g_B2bh[1024],  g_B2bl[1024];
__device__ __align__(16) __half g_Bc1h[32768], g_Bc1l[32768];
__device__ __align__(16) __half g_Bc2h[65536], g_Bc2l[65536];

__device__ __forceinline__ uint32_t smem_u32(const void* p) {
    uint32_t a;
    asm("{ .reg .u64 t; cvta.to.shared.u64 t, %1; cvt.u32.u64 %0, t; }" : "=r"(a) : "l"(p));
    return a;
}
#define LDSM4(r, addr)                                                           \
    asm volatile("ldmatrix.sync.aligned.m8n8.x4.shared.b16 {%0,%1,%2,%3}, [%4];" \
        : "=r"((r)[0]), "=r"((r)[1]), "=r"((r)[2]), "=r"((r)[3]) : "r"(addr))
#define MMA16816(d, a, b0, b1)                                                   \
    asm volatile("mma.sync.aligned.m16n8k16.row.col.f32.f16.f16.f32 "            \
        "{%0,%1,%2,%3}, {%4,%5,%6,%7}, {%8,%9}, {%0,%1,%2,%3};"                  \
        : "+f"((d)[0]), "+f"((d)[1]), "+f"((d)[2]), "+f"((d)[3])                  \
        : "r"((a)[0]), "r"((a)[1]), "r"((a)[2]), "r"((a)[3]), "r"(b0), "r"(b1))
#define CP16(sa, g)                                                              \
    asm volatile("cp.async.cg.shared.global [%0], [%1], 16;" :: "r"(sa), "l"(g))
#define CP_COMMIT() asm volatile("cp.async.commit_group;" ::: "memory")
#define CP_WAIT1()  asm volatile("cp.async.wait_group 1;" ::: "memory")
#define CP_WAIT0()  asm volatile("cp.async.wait_group 0;" ::: "memory")

__device__ __forceinline__ uint32_t pack2h(__half a, __half b) {
    return (uint32_t)__half_as_ushort(a) | ((uint32_t)__half_as_ushort(b) << 16);
}
__device__ __forceinline__ void hsplit(float v, __half& h, __half& l) {
    h = __float2half_rn(v); l = __float2half_rn(v - __half2float(h));
}
__device__ __forceinline__ float hswish(float v) {
    return v * fminf(fmaxf(v + 3.f, 0.f), 6.f) * (1.f / 6.f);
}
__device__ __forceinline__ void store1(char* p, int idx, float v) {
    *(__half*)(p + idx * 2) = __float2half_rn(v);
}
__device__ __forceinline__ void cvt4(char* p, uint32_t off, float4 v) {
    uint2 u;
    u.x = pack2h(__float2half_rn(v.x), __float2half_rn(v.y));
    u.y = pack2h(__float2half_rn(v.z), __float2half_rn(v.w));
    *(uint2*)(p + off) = u;
}

__global__ void prep_k(const float* __restrict__ W0a, const float* __restrict__ W0b,
                       const float* __restrict__ W1a, const float* __restrict__ W1b,
                       const float* __restrict__ W2a, const float* __restrict__ W2b,
                       const float* __restrict__ c1w, const float* __restrict__ c2w) {
    int tid = blockIdx.x * blockDim.x + threadIdx.x, st = gridDim.x * blockDim.x;
    for (int i = tid; i < 16384; i += st) {
        int n = i >> 7, k = i & 127; float m = (k <= n) ? 1.f : 0.f;
        hsplit(m * W0a[i], g_B0ah[i], g_B0al[i]);
        hsplit(m * W0b[i], g_B0bh[i], g_B0bl[i]);
    }
    for (int i = tid; i < 4096; i += st) {
        int n = i >> 6, k = i & 63; float m = (k <= n) ? 1.f : 0.f;
        hsplit(m * W1a[i], g_B1ah[i], g_B1al[i]);
        hsplit(m * W1b[i], g_B1bh[i], g_B1bl[i]);
    }
    for (int i = tid; i < 1024; i += st) {
        int n = i >> 5, k = i & 31; float m = (k <= n) ? 1.f : 0.f;
        hsplit(m * W2a[i], g_B2ah[i], g_B2al[i]);
        hsplit(m * W2b[i], g_B2bh[i], g_B2bl[i]);
    }
    for (int i = tid; i < 32768; i += st) {
        int co = i >> 8, k = i & 255;
        hsplit(c1w[co * 256 + (k & 127) * 2 + (k >> 7)], g_Bc1h[i], g_Bc1l[i]);
    }
    for (int i = tid; i < 65536; i += st) {
        int co = i >> 9, k = i & 511;
        hsplit(c2w[co * 512 + (k & 127) * 4 + (k >> 7)], g_Bc2h[i], g_Bc2l[i]);
    }
}

// sync-load a B tile (small triu GEMMs), hi+lo planes
template<int NROWS, int KCH, int SBH>
__device__ __forceinline__ void load_b(char* pBh, char* pBl,
    const __half* __restrict__ gh, const __half* __restrict__ gl,
    int ktot, int kbase, int tid) {
    constexpr int PER = KCH / 8, TOT = NROWS * PER;
    for (int i = tid; i < TOT; i += 256) {
        int n = i / PER, kq = i % PER;
        uint32_t off = (uint32_t)(n * SBH + kq * 8) * 2;
        *(uint4*)(pBh + off) = *(const uint4*)(gh + n * ktot + kbase + kq * 8);
        *(uint4*)(pBl + off) = *(const uint4*)(gl + n * ktot + kbase + kq * 8);
    }
}

// async-load one K=32 B chunk of NR rows starting at gmem row `rowbase`.
// local rows < nmin are skipped (tril zeros; matching MMA blocks are skipped).
template<int NR>
__device__ __forceinline__ void cpb32g(uint32_t sh, uint32_t sl,
    const __half* __restrict__ gh, const __half* __restrict__ gl,
    int ktot, int kbase, int rowbase, int nmin, int tid) {
    constexpr int TOT = NR * 4;
    for (int i = tid; i < TOT; i += 256) {
        int n = i >> 2, kq = i & 3;
        if (n < nmin) continue;
        uint32_t off = (uint32_t)(n * 40 + kq * 8) * 2;
        const __half* gp = gh + (rowbase + n) * ktot + kbase + kq * 8;
        CP16(sh + off, gp);
        CP16(sl + off, gl + (gp - gh));
    }
}

// 2-pass MMA over KS k16-steps. A single plane (k-index ksA+kk local to A
// region); B chunk-local (stride SBH, index kk). TRI skip when global k16
// (kg+kk) > global col group (gbase+gg).
template<int KS, int RB, int NG, int WC, int SAH, int SBH, bool TRI>
__device__ __forceinline__ void mma2(uint32_t uA, uint32_t uBh, uint32_t uBl,
    uint32_t aoff, uint32_t boff, int wcp, int ksA, int kg, int gbase,
    float (*acc)[4]) {
#pragma unroll
    for (int kk = 0; kk < KS; kk++) {
        int ka = ksA + kk, kt = kg + kk;
        uint32_t ah[RB][4];
        if (!TRI || kt <= gbase + (NG - 1) * WC + wcp) {
#pragma unroll
            for (int rb = 0; rb < RB; rb++)
                LDSM4(ah[rb], uA + aoff + rb * (16 * SAH * 2) + (uint32_t)ka * 32);
        }
#pragma unroll
        for (int g = 0; g < NG; g++) {
            int gg = g * WC + wcp;
            if (TRI && kt > gbase + gg) continue;
            uint32_t bh[4], bl[4];
            LDSM4(bh, uBh + boff + (uint32_t)(gg * (16 * SBH * 2) + kk * 32));
            LDSM4(bl, uBl + boff + (uint32_t)(gg * (16 * SBH * 2) + kk * 32));
#pragma unroll
            for (int rb = 0; rb < RB; rb++) {
                float* a0 = acc[(rb * NG + g) * 2]; float* a1 = acc[(rb * NG + g) * 2 + 1];
                MMA16816(a0, ah[rb], bh[0], bh[1]); MMA16816(a1, ah[rb], bh[2], bh[3]);
                MMA16816(a0, ah[rb], bl[0], bl[1]); MMA16816(a1, ah[rb], bl[2], bl[3]);
            }
        }
    }
}

// pipelined half-GEMM over global chunk range [c0,c1); A region local k starts
// at chunk c0. B rows [rowbase, rowbase+NR) with tril row pruning.
template<int NR, int RB, int NG, int WC, int SAH, bool TRI>
__device__ __forceinline__ void hg(uint32_t uA, uint32_t aoff,
    uint32_t b0h, uint32_t b0l, uint32_t b1h, uint32_t b1l,
    const __half* __restrict__ gh, const __half* __restrict__ gl,
    int ktot, int rowbase, int c0, int c1,
    uint32_t boff, int wcp, int tid, float (*acc)[4]) {
    const int gbase = rowbase >> 4;
    cpb32g<NR>(b0h, b0l, gh, gl, ktot, c0 * 32, rowbase,
               TRI ? max(0, 32 * c0 - rowbase) : 0, tid);
    CP_COMMIT();
#pragma unroll 1
    for (int c = c0; c < c1; c++) {
        int idx = (c - c0) & 1;
        if (c + 1 < c1) {
            uint32_t nh = idx ? b0h : b1h, nl = idx ? b0l : b1l;
            cpb32g<NR>(nh, nl, gh, gl, ktot, (c + 1) * 32, rowbase,
                       TRI ? max(0, 32 * (c + 1) - rowbase) : 0, tid);
            CP_COMMIT(); CP_WAIT1();
        } else CP_WAIT0();
        __syncthreads();
        uint32_t bh = idx ? b1h : b0h, bl = idx ? b1l : b0l;
        mma2<2, RB, NG, WC, SAH, 40, TRI>(uA, bh, bl, aoff, boff, wcp,
                                          (c - c0) * 2, c * 2, gbase, acc);
        __syncthreads();
    }
}

template<int NA> __device__ __forceinline__ void zacc(float (*acc)[4]) {
#pragma unroll
    for (int i = 0; i < NA; i++) { acc[i][0] = acc[i][1] = acc[i][2] = acc[i][3] = 0.f; }
}

template<int RB, int NG, int WC, bool HSW, class F>
__device__ __forceinline__ void epi(float (*acc)[4], const float* sb,
                                    int r0, int wcp, int lane, F f) {
#pragma unroll
    for (int rb = 0; rb < RB; rb++)
#pragma unroll
    for (int g = 0; g < NG; g++)
#pragma unroll
    for (int j = 0; j < 2; j++) {
        const float* a = acc[(rb * NG + g) * 2 + j];
        int cc = (g * WC + wcp) * 16 + j * 8 + 2 * (lane & 3);
        int r = r0 + rb * 16 + (lane >> 2);
        float b0 = sb[cc], b1 = sb[cc + 1];
        float v0 = a[0] + b0, v1 = a[1] + b1, v2 = a[2] + b0, v3 = a[3] + b1;
        if (HSW) { v0 = hswish(v0); v1 = hswish(v1); v2 = hswish(v2); v3 = hswish(v3); }
        f(r, cc, v0); f(r, cc + 1, v1); f(r + 8, cc, v2); f(r + 8, cc + 1, v3);
    }
}

// ---------------------------------------------------------------------------
// mega kernel: one CTA = one batch. dsmem = 74752 B, 3 CTAs/SM.
// ---------------------------------------------------------------------------
__global__ __launch_bounds__(256, 3)
void mega_kernel(const float* __restrict__ x, const float* __restrict__ lg,
                 const float* __restrict__ lb,
                 const float* __restrict__ b0a, const float* __restrict__ b0b,
                 const float* __restrict__ c1b, const float* __restrict__ b1a,
                 const float* __restrict__ b1b,
                 const float* __restrict__ c2b, const float* __restrict__ b2a,
                 const float* __restrict__ b2b,
                 float* __restrict__ out) {
    extern __shared__ char dsm[];
    __shared__ float s_s[8], s_q[8], s_ms[2], s_b1[128], s_b2[128], s_b3[128];
    const int tid = threadIdx.x, lane = tid & 31, wid = tid >> 5;
    const int b = blockIdx.x;
    const uint32_t u0 = smem_u32(dsm);
    const float* xbf = x + (long long)b * 16384;
    float acc[8][4];

    const int arow = ((lane >> 3) & 1) * 8 + (lane & 7);
    const int acol8 = (lane >> 4) * 8;
    const int brow = (lane >> 4) * 8 + (lane & 7);
    const int bcol8 = ((lane >> 3) & 1) * 8;
    const uint32_t boff40 = (uint32_t)(brow * 40 + bcol8) * 2;

    //======================= phase 0: scale 0 ==============================
    // A (LN(x), fp16) 128x136 at [0,34816); B bufs 64x40 at 34816/39936/
    // 45056/50176; T2 128x72 at [55296,73728).
    // GEMM halves (N=64): GEMM1 half1 -> T2; GEMM1 half0 -> A cols 64..127;
    // GEMM2 reads T from those two regions.
    {
        const int r0 = (wid & 3) * 32, wcp = wid >> 2;
        char* pA = dsm;
        char* pT2 = dsm + 55296;
        const uint32_t uA = u0, uA1 = u0 + 128, uT2 = u0 + 55296;
        const uint32_t b0h = u0 + 34816, b0l = u0 + 39936;
        const uint32_t b1h = u0 + 45056, b1l = u0 + 50176;
        const uint32_t aoff = (uint32_t)((r0 + arow) * 136 + acol8) * 2;
        const uint32_t aoffT2 = (uint32_t)((r0 + arow) * 72 + acol8) * 2;
        if (tid < 128) { s_b1[tid] = b0a[tid]; s_b2[tid] = b0b[tid]; }

        const float4* xb = (const float4*)xbf;
        float sm = 0.f, sq = 0.f;
#pragma unroll
        for (int q = 0; q < 16; q++) {
            float4 v = xb[q * 256 + tid];
            sm += v.x + v.y + v.z + v.w;
            sq += v.x * v.x + v.y * v.y + v.z * v.z + v.w * v.w;
        }
#pragma unroll
        for (int o = 16; o > 0; o >>= 1) {
            sm += __shfl_down_sync(~0u, sm, o); sq += __shfl_down_sync(~0u, sq, o);
        }
        if (lane == 0) { s_s[wid] = sm; s_q[wid] = sq; }
        __syncthreads();
        if (tid == 0) {
            float S = 0.f, Q = 0.f;
#pragma unroll
            for (int i = 0; i < 8; i++) { S += s_s[i]; Q += s_q[i]; }
            float mu = S * (1.f / 16384.f);
            s_ms[0] = mu; s_ms[1] = rsqrtf(Q * (1.f / 16384.f) - mu * mu + 1e-5f);
        }
        __syncthreads();
        const float mu = s_ms[0], rs = s_ms[1];
#pragma unroll
        for (int qq = 0; qq < 16; qq++) {
            int q = qq * 256 + tid;
            int r = q >> 5, col = (q & 31) * 4;
            float4 v = xb[q];
            float4 g = *(const float4*)(lg + r * 128 + col);
            float4 be = *(const float4*)(lb + r * 128 + col);
            v.x = (v.x - mu) * rs * g.x + be.x; v.y = (v.y - mu) * rs * g.y + be.y;
            v.z = (v.z - mu) * rs * g.z + be.z; v.w = (v.w - mu) * rs * g.w + be.w;
            cvt4(pA, (uint32_t)(r * 136 + col) * 2, v);
        }

        // GEMM1 half1 (cols 64..127, full K) -> T2
        zacc<8>(acc);
        hg<64, 2, 2, 2, 136, true>(uA, aoff, b0h, b0l, b1h, b1l,
            g_B0ah, g_B0al, 128, 64, 0, 4, boff40, wcp, tid, acc);
        epi<2, 2, 2, true>(acc, s_b1 + 64, r0, wcp, lane,
            [&](int r, int c, float v) { store1(pT2, r * 72 + c, v); });

        // GEMM1 half0 (cols 0..63, K<64) -> A cols 64..127 (dead region)
        zacc<8>(acc);
        hg<64, 2, 2, 2, 136, true>(uA, aoff, b0h, b0l, b1h, b1l,
            g_B0ah, g_B0al, 128, 0, 0, 2, boff40, wcp, tid, acc);
        epi<2, 2, 2, true>(acc, s_b1, r0, wcp, lane,
            [&](int r, int c, float v) { store1(pA, r * 136 + 64 + c, v); });

        float* ob = out + (long long)b * 28672;
        // GEMM2 half1 (cols 64..127): K 0-63 from region1, 64-127 from T2
        zacc<8>(acc);
        hg<64, 2, 2, 2, 136, true>(uA1, aoff, b0h, b0l, b1h, b1l,
            g_B0bh, g_B0bl, 128, 64, 0, 2, boff40, wcp, tid, acc);
        hg<64, 2, 2, 2, 72, true>(uT2, aoffT2, b0h, b0l, b1h, b1l,
            g_B0bh, g_B0bl, 128, 64, 2, 4, boff40, wcp, tid, acc);
        epi<2, 2, 2, false>(acc, s_b2 + 64, r0, wcp, lane,
            [&](int r, int c, float v) { ob[(64 + c) * 128 + r] = v; });

        // GEMM2 half0 (cols 0..63, K<64 from region1)
        zacc<8>(acc);
        hg<64, 2, 2, 2, 136, true>(uA1, aoff, b0h, b0l, b1h, b1l,
            g_B0bh, g_B0bl, 128, 0, 0, 2, boff40, wcp, tid, acc);
        epi<2, 2, 2, false>(acc, s_b2, r0, wcp, lane,
            [&](int r, int c, float v) { ob[c * 128 + r] = v; });
    }

    //======================= phase 1: scale 1 ==============================
    // conv A 64x264 at [0,33792); B bufs 128x40 at 33792/44032/54272/64512.
    // post-conv: A2 128x72 [0,18432); A3 [18432,36864); triB [36864,55296).
    {
        __syncthreads();
        const int r0c = (wid & 1) * 32, wcpc = wid >> 1;
        const int r0t = (wid & 3) * 32, wcpt = wid >> 2;
        char* pC = dsm;
        char* pA2 = dsm;          char* pA3 = dsm + 18432;
        char* pTBh = dsm + 36864; char* pTBl = dsm + 46080;
        const uint32_t uC = u0, uA2 = u0, uA3 = u0 + 18432;
        const uint32_t uTBh = u0 + 36864, uTBl = u0 + 46080;
        const uint32_t b0h = u0 + 33792, b0l = u0 + 44032;
        const uint32_t b1h = u0 + 54272, b1l = u0 + 64512;
        const uint32_t aoffc = (uint32_t)((r0c + arow) * 264 + acol8) * 2;
        const uint32_t aofft = (uint32_t)((r0t + arow) * 72 + acol8) * 2;
        const uint32_t bofft = (uint32_t)(brow * 72 + bcol8) * 2;
        if (tid < 128) s_b1[tid] = c1b[tid];
        if (tid < 64) { s_b2[tid] = b1a[tid]; s_b3[tid] = b1b[tid]; }

        const float4* xb = (const float4*)xbf;
#pragma unroll
        for (int qq = 0; qq < 16; qq++) {
            int q = qq * 256 + tid;
            int r = q >> 6, col = (q & 63) * 4;
            cvt4(pC, (uint32_t)(r * 264 + col) * 2, xb[q]);
        }

        zacc<8>(acc);
        hg<128, 2, 2, 4, 264, false>(uC, aoffc, b0h, b0l, b1h, b1l,
            g_Bc1h, g_Bc1l, 256, 0, 0, 8, boff40, wcpc, tid, acc);
        epi<2, 2, 4, false>(acc, s_b1, r0c, wcpc, lane,
            [&](int r, int c, float v) { store1(pA2, c * 72 + r, v); });

        zacc<8>(acc);
        load_b<64, 64, 72>(pTBh, pTBl, g_B1ah, g_B1al, 64, 0, tid);
        __syncthreads();
        mma2<4, 2, 2, 2, 72, 72, true>(uA2, uTBh, uTBl, aofft, bofft, wcpt, 0, 0, 0, acc);
        __syncthreads();
        epi<2, 2, 2, true>(acc, s_b2, r0t, wcpt, lane,
            [&](int r, int c, float v) { store1(pA3, r * 72 + c, v); });

        zacc<8>(acc);
        load_b<64, 64, 72>(pTBh, pTBl, g_B1bh, g_B1bl, 64, 0, tid);
        __syncthreads();
        mma2<4, 2, 2, 2, 72, 72, true>(uA3, uTBh, uTBl, aofft, bofft, wcpt, 0, 0, 0, acc);
        float* ob = out + (long long)b * 28672 + 16384;
        epi<2, 2, 2, false>(acc, s_b3, r0t, wcpt, lane,
            [&](int r, int c, float v) { ob[c * 128 + r] = v; });
    }

    //======================= phase 2: scale 2 ==============================
    // conv A 32x520 at [0,33280); B bufs at 33280/43520/53760/64000.
    // post-conv: A2 128x40 [0,10240); A3 [10240,20480); triB [20480,25600).
    {
        __syncthreads();
        const int r0c = (wid & 1) * 16, wcpc = wid >> 1;
        const int r0t = wid * 16;
        char* pC = dsm;
        char* pA2 = dsm;          char* pA3 = dsm + 10240;
        char* pTBh = dsm + 20480; char* pTBl = dsm + 23040;
        const uint32_t uC = u0, uA2 = u0, uA3 = u0 + 10240;
        const uint32_t uTBh = u0 + 20480, uTBl = u0 + 23040;
        const uint32_t b0h = u0 + 33280, b0l = u0 + 43520;
        const uint32_t b1h = u0 + 53760, b1l = u0 + 64000;
        const uint32_t aoffc = (uint32_t)((r0c + arow) * 520 + acol8) * 2;
        const uint32_t aofft = (uint32_t)((r0t + arow) * 40 + acol8) * 2;
        if (tid < 128) s_b1[tid] = c2b[tid];
        if (tid < 32) { s_b2[tid] = b2a[tid]; s_b3[tid] = b2b[tid]; }

#pragma unroll
        for (int qq = 0; qq < 16; qq++) {
            int q = qq * 256 + tid;
            int r = q >> 7, col = (q & 127) * 4;
            float4 v = *(const float4*)(xbf + r * 512 + col);
            cvt4(pC, (uint32_t)(r * 520 + col) * 2, v);
        }

        zacc<8>(acc);
        hg<128, 1, 2, 4, 520, false>(uC, aoffc, b0h, b0l, b1h, b1l,
            g_Bc2h, g_Bc2l, 512, 0, 0, 16, boff40, wcpc, tid, acc);
        epi<1, 2, 4, false>(acc, s_b1, r0c, wcpc, lane,
            [&](int r, int c, float v) { store1(pA2, c * 40 + r, v); });

        zacc<8>(acc);
        load_b<32, 32, 40>(pTBh, pTBl, g_B2ah, g_B2al, 32, 0, tid);
        __syncthreads();
        mma2<2, 1, 2, 1, 40, 40, true>(uA2, uTBh, uTBl, aofft, boff40, 0, 0, 0, 0, acc);
        __syncthreads();
        epi<1, 2, 1, true>(acc, s_b2, r0t, 0, lane,
            [&](int r, int c, float v) { store1(pA3, r * 40 + c, v); });

        zacc<8>(acc);
        load_b<32, 32, 40>(pTBh, pTBl, g_B2bh, g_B2bl, 32, 0, tid);
        __syncthreads();
        mma2<2, 1, 2, 1, 40, 40, true>(uA3, uTBh, uTBl, aofft, boff40, 0, 0, 0, 0, acc);
        float* ob = out + (long long)b * 28672 + 24576;
        epi<1, 2, 1, false>(acc, s_b3, r0t, 0, lane,
            [&](int r, int c, float v) { ob[c * 128 + r] = v; });
    }
}

// ---------------------------------------------------------------------------
extern "C" void kernel_launch(void* const* d_in, const int* in_sizes, int n_in,
                              void* d_out, int out_size) {
    const float* x   = (const float*)d_in[0];
    const float* lg  = (const float*)d_in[1];
    const float* lb  = (const float*)d_in[2];
    const float* W0a = (const float*)d_in[3];
    const float* b0a = (const float*)d_in[4];
    const float* W0b = (const float*)d_in[5];
    const float* b0b = (const float*)d_in[6];
    const float* c1w = (const float*)d_in[7];
    const float* c1b = (const float*)d_in[8];
    const float* W1a = (const float*)d_in[9];
    const float* b1a = (const float*)d_in[10];
    const float* W1b = (const float*)d_in[11];
    const float* b1b = (const float*)d_in[12];
    const float* c2w = (const float*)d_in[13];
    const float* c2b = (const float*)d_in[14];
    const float* W2a = (const float*)d_in[15];
    const float* b2a = (const float*)d_in[16];
    const float* W2b = (const float*)d_in[17];
    const float* b2b = (const float*)d_in[18];
    float* out = (float*)d_out;

    const int ds = 74752;
    cudaFuncSetAttribute(mega_kernel, cudaFuncAttributeMaxDynamicSharedMemorySize, ds);

    prep_k<<<128, 256>>>(W0a, W0b, W1a, W1b, W2a, W2b, c1w, c2w);
    mega_kernel<<<2048, 256, ds>>>(x, lg, lb, b0a, b0b, c1b, b1a, b1b,
                                   c2b, b2a, b2b, out);
}

// round 15
// speedup vs baseline: 1.7111x; 1.2863x over previous
#include <cuda_runtime.h>
#include <cuda_fp16.h>
#include <cstdint>

// MultiScaleTimeMixer: fused mega-kernel (1 batch/CTA, 3 phases).
// Pure fp16 1-pass MMA (A and W both fp16-rn), fp32 acc.
// K=64 double-buffered cp.async weight chunks. 3 CTAs/SM (71680 B dsmem).

__device__ __align__(16) __half g_B0a[16384], g_B0b[16384];
__device__ __align__(16) __half g_B1a[4096],  g_B1b[4096];
__device__ __align__(16) __half g_B2a[1024],  g_B2b[1024];
__device__ __align__(16) __half g_Bc1[32768], g_Bc2[65536];

__device__ __forceinline__ uint32_t smem_u32(const void* p) {
    uint32_t a;
    asm("{ .reg .u64 t; cvta.to.shared.u64 t, %1; cvt.u32.u64 %0, t; }" : "=r"(a) : "l"(p));
    return a;
}
#define LDSM4(r, addr)                                                           \
    asm volatile("ldmatrix.sync.aligned.m8n8.x4.shared.b16 {%0,%1,%2,%3}, [%4];" \
        : "=r"((r)[0]), "=r"((r)[1]), "=r"((r)[2]), "=r"((r)[3]) : "r"(addr))
#define MMA16816(d, a, b0, b1)                                                   \
    asm volatile("mma.sync.aligned.m16n8k16.row.col.f32.f16.f16.f32 "            \
        "{%0,%1,%2,%3}, {%4,%5,%6,%7}, {%8,%9}, {%0,%1,%2,%3};"                  \
        : "+f"((d)[0]), "+f"((d)[1]), "+f"((d)[2]), "+f"((d)[3])                  \
        : "r"((a)[0]), "r"((a)[1]), "r"((a)[2]), "r"((a)[3]), "r"(b0), "r"(b1))
#define CP16(sa, g)                                                              \
    asm volatile("cp.async.cg.shared.global [%0], [%1], 16;" :: "r"(sa), "l"(g))
#define CP_COMMIT() asm volatile("cp.async.commit_group;" ::: "memory")
#define CP_WAIT1()  asm volatile("cp.async.wait_group 1;" ::: "memory")
#define CP_WAIT0()  asm volatile("cp.async.wait_group 0;" ::: "memory")

__device__ __forceinline__ uint32_t pack2h(__half a, __half b) {
    return (uint32_t)__half_as_ushort(a) | ((uint32_t)__half_as_ushort(b) << 16);
}
__device__ __forceinline__ float hswish(float v) {
    return v * fminf(fmaxf(v + 3.f, 0.f), 6.f) * (1.f / 6.f);
}
__device__ __forceinline__ void store1(char* p, int idx, float v) {
    *(__half*)(p + idx * 2) = __float2half_rn(v);
}
__device__ __forceinline__ void cvt4(char* p, uint32_t off, float4 v) {
    uint2 u;
    u.x = pack2h(__float2half_rn(v.x), __float2half_rn(v.y));
    u.y = pack2h(__float2half_rn(v.z), __float2half_rn(v.w));
    *(uint2*)(p + off) = u;
}

__global__ void prep_k(const float* __restrict__ W0a, const float* __restrict__ W0b,
                       const float* __restrict__ W1a, const float* __restrict__ W1b,
                       const float* __restrict__ W2a, const float* __restrict__ W2b,
                       const float* __restrict__ c1w, const float* __restrict__ c2w) {
    int tid = blockIdx.x * blockDim.x + threadIdx.x, st = gridDim.x * blockDim.x;
    for (int i = tid; i < 16384; i += st) {
        int n = i >> 7, k = i & 127; float m = (k <= n) ? 1.f : 0.f;
        g_B0a[i] = __float2half_rn(m * W0a[i]);
        g_B0b[i] = __float2half_rn(m * W0b[i]);
    }
    for (int i = tid; i < 4096; i += st) {
        int n = i >> 6, k = i & 63; float m = (k <= n) ? 1.f : 0.f;
        g_B1a[i] = __float2half_rn(m * W1a[i]);
        g_B1b[i] = __float2half_rn(m * W1b[i]);
    }
    for (int i = tid; i < 1024; i += st) {
        int n = i >> 5, k = i & 31; float m = (k <= n) ? 1.f : 0.f;
        g_B2a[i] = __float2half_rn(m * W2a[i]);
        g_B2b[i] = __float2half_rn(m * W2b[i]);
    }
    for (int i = tid; i < 32768; i += st) {
        int co = i >> 8, k = i & 255;
        g_Bc1[i] = __float2half_rn(c1w[co * 256 + (k & 127) * 2 + (k >> 7)]);
    }
    for (int i = tid; i < 65536; i += st) {
        int co = i >> 9, k = i & 511;
        g_Bc2[i] = __float2half_rn(c2w[co * 512 + (k & 127) * 4 + (k >> 7)]);
    }
}

// sync-load a B tile (small triu GEMMs), single plane
template<int NROWS, int KCH, int SBH>
__device__ __forceinline__ void load_b1(char* pB, const __half* __restrict__ g,
    int ktot, int kbase, int tid) {
    constexpr int PER = KCH / 8, TOT = NROWS * PER;
    for (int i = tid; i < TOT; i += 256) {
        int n = i / PER, kq = i % PER;
        *(uint4*)(pB + (uint32_t)(n * SBH + kq * 8) * 2) =
            *(const uint4*)(g + n * ktot + kbase + kq * 8);
    }
}

// async-load one K=64 B chunk (stride 72 halves). local rows < nmin skipped.
template<int NR>
__device__ __forceinline__ void cpb64(uint32_t s, const __half* __restrict__ g,
    int ktot, int kbase, int rowbase, int nmin, int tid) {
    constexpr int TOT = NR * 8;
    for (int i = tid; i < TOT; i += 256) {
        int n = i >> 3, kq = i & 7;
        if (n < nmin) continue;
        CP16(s + (uint32_t)(n * 72 + kq * 8) * 2,
             g + (rowbase + n) * ktot + kbase + kq * 8);
    }
}

// 1-pass MMA over KS k16-steps. A (k-index ksA+kk local to A region);
// B chunk-local (stride SBH, index kk). TRI skip when global k16 (kg+kk)
// > global col group (gbase + gg).
template<int KS, int RB, int NG, int WC, int SAH, int SBH, bool TRI>
__device__ __forceinline__ void mma1(uint32_t uA, uint32_t uB,
    uint32_t aoff, uint32_t boff, int wcp, int ksA, int kg, int gbase,
    float (*acc)[4]) {
#pragma unroll
    for (int kk = 0; kk < KS; kk++) {
        int ka = ksA + kk, kt = kg + kk;
        uint32_t ah[RB][4];
        if (!TRI || kt <= gbase + (NG - 1) * WC + wcp) {
#pragma unroll
            for (int rb = 0; rb < RB; rb++)
                LDSM4(ah[rb], uA + aoff + rb * (16 * SAH * 2) + (uint32_t)ka * 32);
        }
#pragma unroll
        for (int g = 0; g < NG; g++) {
            int gg = g * WC + wcp;
            if (TRI && kt > gbase + gg) continue;
            uint32_t bh[4];
            LDSM4(bh, uB + boff + (uint32_t)(gg * (16 * SBH * 2) + kk * 32));
#pragma unroll
            for (int rb = 0; rb < RB; rb++) {
                MMA16816(acc[(rb * NG + g) * 2], ah[rb], bh[0], bh[1]);
                MMA16816(acc[(rb * NG + g) * 2 + 1], ah[rb], bh[2], bh[3]);
            }
        }
    }
}

// pipelined GEMM over global K=64 chunk range [c0,c1); A region local k
// starts at chunk c0. B rows [rowbase, rowbase+NR) with tril row pruning.
template<int NR, int RB, int NG, int WC, int SAH, bool TRI>
__device__ __forceinline__ void hg(uint32_t uA, uint32_t aoff,
    uint32_t b0, uint32_t b1,
    const __half* __restrict__ g, int ktot, int rowbase, int c0, int c1,
    uint32_t boff, int wcp, int tid, float (*acc)[4]) {
    const int gbase = rowbase >> 4;
    cpb64<NR>(b0, g, ktot, c0 * 64, rowbase,
              TRI ? max(0, 64 * c0 - rowbase) : 0, tid);
    CP_COMMIT();
#pragma unroll 1
    for (int c = c0; c < c1; c++) {
        int idx = (c - c0) & 1;
        if (c + 1 < c1) {
            cpb64<NR>(idx ? b0 : b1, g, ktot, (c + 1) * 64, rowbase,
                      TRI ? max(0, 64 * (c + 1) - rowbase) : 0, tid);
            CP_COMMIT(); CP_WAIT1();
        } else CP_WAIT0();
        __syncthreads();
        mma1<4, RB, NG, WC, SAH, 72, TRI>(uA, idx ? b1 : b0, aoff, boff, wcp,
                                          (c - c0) * 4, c * 4, gbase, acc);
        __syncthreads();
    }
}

template<int NA> __device__ __forceinline__ void zacc(float (*acc)[4]) {
#pragma unroll
    for (int i = 0; i < NA; i++) { acc[i][0] = acc[i][1] = acc[i][2] = acc[i][3] = 0.f; }
}

template<int RB, int NG, int WC, bool HSW, class F>
__device__ __forceinline__ void epi(float (*acc)[4], const float* sb,
                                    int r0, int wcp, int lane, F f) {
#pragma unroll
    for (int rb = 0; rb < RB; rb++)
#pragma unroll
    for (int g = 0; g < NG; g++)
#pragma unroll
    for (int j = 0; j < 2; j++) {
        const float* a = acc[(rb * NG + g) * 2 + j];
        int cc = (g * WC + wcp) * 16 + j * 8 + 2 * (lane & 3);
        int r = r0 + rb * 16 + (lane >> 2);
        float b0 = sb[cc], b1 = sb[cc + 1];
        float v0 = a[0] + b0, v1 = a[1] + b1, v2 = a[2] + b0, v3 = a[3] + b1;
        if (HSW) { v0 = hswish(v0); v1 = hswish(v1); v2 = hswish(v2); v3 = hswish(v3); }
        f(r, cc, v0); f(r, cc + 1, v1); f(r + 8, cc, v2); f(r + 8, cc + 1, v3);
    }
}

// ---------------------------------------------------------------------------
// mega kernel: one CTA = one batch. dsmem = 71680 B, 3 CTAs/SM.
// ---------------------------------------------------------------------------
__global__ __launch_bounds__(256, 3)
void mega_kernel(const float* __restrict__ x, const float* __restrict__ lg,
                 const float* __restrict__ lb,
                 const float* __restrict__ b0a, const float* __restrict__ b0b,
                 const float* __restrict__ c1b, const float* __restrict__ b1a,
                 const float* __restrict__ b1b,
                 const float* __restrict__ c2b, const float* __restrict__ b2a,
                 const float* __restrict__ b2b,
                 float* __restrict__ out) {
    extern __shared__ char dsm[];
    __shared__ float s_s[8], s_q[8], s_ms[2], s_b1[128], s_b2[128], s_b3[128];
    const int tid = threadIdx.x, lane = tid & 31, wid = tid >> 5;
    const int b = blockIdx.x;
    const uint32_t u0 = smem_u32(dsm);
    const float* xbf = x + (long long)b * 16384;
    float acc[8][4];

    const int arow = ((lane >> 3) & 1) * 8 + (lane & 7);
    const int acol8 = (lane >> 4) * 8;
    const int brow = (lane >> 4) * 8 + (lane & 7);
    const int bcol8 = ((lane >> 3) & 1) * 8;
    const uint32_t boff72 = (uint32_t)(brow * 72 + bcol8) * 2;
    const uint32_t boff40 = (uint32_t)(brow * 40 + bcol8) * 2;

    //======================= phase 0: scale 0 ==============================
    // A (LN(x) fp16) 128x136 at [0,34816); B bufs 64x72 at 34816 / 44032;
    // T2 128x72 at [53248,71680).
    // GEMM halves (N=64): GEMM1 half1 -> T2; GEMM1 half0 -> A cols 64..127;
    // GEMM2 reads T from those two regions.
    {
        const int r0 = (wid & 3) * 32, wcp = wid >> 2;
        char* pA = dsm;
        char* pT2 = dsm + 53248;
        const uint32_t uA = u0, uA1 = u0 + 128, uT2 = u0 + 53248;
        const uint32_t b0 = u0 + 34816, b1 = u0 + 44032;
        const uint32_t aoff = (uint32_t)((r0 + arow) * 136 + acol8) * 2;
        const uint32_t aoffT2 = (uint32_t)((r0 + arow) * 72 + acol8) * 2;
        if (tid < 128) { s_b1[tid] = b0a[tid]; s_b2[tid] = b0b[tid]; }

        const float4* xb = (const float4*)xbf;
        float sm = 0.f, sq = 0.f;
#pragma unroll
        for (int q = 0; q < 16; q++) {
            float4 v = xb[q * 256 + tid];
            sm += v.x + v.y + v.z + v.w;
            sq += v.x * v.x + v.y * v.y + v.z * v.z + v.w * v.w;
        }
#pragma unroll
        for (int o = 16; o > 0; o >>= 1) {
            sm += __shfl_down_sync(~0u, sm, o); sq += __shfl_down_sync(~0u, sq, o);
        }
        if (lane == 0) { s_s[wid] = sm; s_q[wid] = sq; }
        __syncthreads();
        if (tid == 0) {
            float S = 0.f, Q = 0.f;
#pragma unroll
            for (int i = 0; i < 8; i++) { S += s_s[i]; Q += s_q[i]; }
            float mu = S * (1.f / 16384.f);
            s_ms[0] = mu; s_ms[1] = rsqrtf(Q * (1.f / 16384.f) - mu * mu + 1e-5f);
        }
        __syncthreads();
        const float mu = s_ms[0], rs = s_ms[1];
#pragma unroll
        for (int qq = 0; qq < 16; qq++) {
            int q = qq * 256 + tid;
            int r = q >> 5, col = (q & 31) * 4;
            float4 v = xb[q];
            float4 g = *(const float4*)(lg + r * 128 + col);
            float4 be = *(const float4*)(lb + r * 128 + col);
            v.x = (v.x - mu) * rs * g.x + be.x; v.y = (v.y - mu) * rs * g.y + be.y;
            v.z = (v.z - mu) * rs * g.z + be.z; v.w = (v.w - mu) * rs * g.w + be.w;
            cvt4(pA, (uint32_t)(r * 136 + col) * 2, v);
        }

        // GEMM1 half1 (cols 64..127, full K=128) -> T2
        zacc<8>(acc);
        hg<64, 2, 2, 2, 136, true>(uA, aoff, b0, b1, g_B0a, 128, 64, 0, 2,
                                   boff72, wcp, tid, acc);
        epi<2, 2, 2, true>(acc, s_b1 + 64, r0, wcp, lane,
            [&](int r, int c, float v) { store1(pT2, r * 72 + c, v); });

        // GEMM1 half0 (cols 0..63, K<64) -> A cols 64..127 (dead region)
        zacc<8>(acc);
        hg<64, 2, 2, 2, 136, true>(uA, aoff, b0, b1, g_B0a, 128, 0, 0, 1,
                                   boff72, wcp, tid, acc);
        epi<2, 2, 2, true>(acc, s_b1, r0, wcp, lane,
            [&](int r, int c, float v) { store1(pA, r * 136 + 64 + c, v); });

        float* ob = out + (long long)b * 28672;
        // GEMM2 half1 (cols 64..127): K 0-63 from A region, 64-127 from T2
        zacc<8>(acc);
        hg<64, 2, 2, 2, 136, true>(uA1, aoff, b0, b1, g_B0b, 128, 64, 0, 1,
                                   boff72, wcp, tid, acc);
        hg<64, 2, 2, 2, 72, true>(uT2, aoffT2, b0, b1, g_B0b, 128, 64, 1, 2,
                                  boff72, wcp, tid, acc);
        epi<2, 2, 2, false>(acc, s_b2 + 64, r0, wcp, lane,
            [&](int r, int c, float v) { ob[(64 + c) * 128 + r] = v; });

        // GEMM2 half0 (cols 0..63, K<64)
        zacc<8>(acc);
        hg<64, 2, 2, 2, 136, true>(uA1, aoff, b0, b1, g_B0b, 128, 0, 0, 1,
                                   boff72, wcp, tid, acc);
        epi<2, 2, 2, false>(acc, s_b2, r0, wcp, lane,
            [&](int r, int c, float v) { ob[c * 128 + r] = v; });
    }

    //======================= phase 1: scale 1 ==============================
    // conv A 64x264 at [0,33792); B bufs 128x72 at 33792 / 52224 (end 70656).
    // post-conv: A2 128x72 [0,18432); A3 [18432,36864); triB [36864,46080).
    {
        __syncthreads();
        const int r0c = (wid & 1) * 32, wcpc = wid >> 1;
        const int r0t = (wid & 3) * 32, wcpt = wid >> 2;
        char* pC = dsm;
        char* pA2 = dsm;          char* pA3 = dsm + 18432;
        char* pTB = dsm + 36864;
        const uint32_t uC = u0, uA2 = u0, uA3 = u0 + 18432;
        const uint32_t uTB = u0 + 36864;
        const uint32_t b0 = u0 + 33792, b1 = u0 + 52224;
        const uint32_t aoffc = (uint32_t)((r0c + arow) * 264 + acol8) * 2;
        const uint32_t aofft = (uint32_t)((r0t + arow) * 72 + acol8) * 2;
        if (tid < 128) s_b1[tid] = c1b[tid];
        if (tid < 64) { s_b2[tid] = b1a[tid]; s_b3[tid] = b1b[tid]; }

        const float4* xb = (const float4*)xbf;
#pragma unroll
        for (int qq = 0; qq < 16; qq++) {
            int q = qq * 256 + tid;
            int r = q >> 6, col = (q & 63) * 4;
            cvt4(pC, (uint32_t)(r * 264 + col) * 2, xb[q]);
        }

        zacc<8>(acc);
        hg<128, 2, 2, 4, 264, false>(uC, aoffc, b0, b1, g_Bc1, 256, 0, 0, 4,
                                     boff72, wcpc, tid, acc);
        epi<2, 2, 4, false>(acc, s_b1, r0c, wcpc, lane,
            [&](int r, int c, float v) { store1(pA2, c * 72 + r, v); });

        zacc<8>(acc);
        load_b1<64, 64, 72>(pTB, g_B1a, 64, 0, tid);
        __syncthreads();
        mma1<4, 2, 2, 2, 72, 72, true>(uA2, uTB, aofft, boff72, wcpt, 0, 0, 0, acc);
        __syncthreads();
        epi<2, 2, 2, true>(acc, s_b2, r0t, wcpt, lane,
            [&](int r, int c, float v) { store1(pA3, r * 72 + c, v); });

        zacc<8>(acc);
        load_b1<64, 64, 72>(pTB, g_B1b, 64, 0, tid);
        __syncthreads();
        mma1<4, 2, 2, 2, 72, 72, true>(uA3, uTB, aofft, boff72, wcpt, 0, 0, 0, acc);
        float* ob = out + (long long)b * 28672 + 16384;
        epi<2, 2, 2, false>(acc, s_b3, r0t, wcpt, lane,
            [&](int r, int c, float v) { ob[c * 128 + r] = v; });
    }

    //======================= phase 2: scale 2 ==============================
    // conv A 32x520 at [0,33280); B bufs 128x72 at 33280 / 51712 (end 70144).
    // post-conv: A2 128x40 [0,10240); A3 [10240,20480); triB [20480,23040).
    {
        __syncthreads();
        const int r0c = (wid & 1) * 16, wcpc = wid >> 1;
        const int r0t = wid * 16;
        char* pC = dsm;
        char* pA2 = dsm;          char* pA3 = dsm + 10240;
        char* pTB = dsm + 20480;
        const uint32_t uC = u0, uA2 = u0, uA3 = u0 + 10240;
        const uint32_t uTB = u0 + 20480;
        const uint32_t b0 = u0 + 33280, b1 = u0 + 51712;
        const uint32_t aoffc = (uint32_t)((r0c + arow) * 520 + acol8) * 2;
        const uint32_t aofft = (uint32_t)((r0t + arow) * 40 + acol8) * 2;
        if (tid < 128) s_b1[tid] = c2b[tid];
        if (tid < 32) { s_b2[tid] = b2a[tid]; s_b3[tid] = b2b[tid]; }

#pragma unroll
        for (int qq = 0; qq < 16; qq++) {
            int q = qq * 256 + tid;
            int r = q >> 7, col = (q & 127) * 4;
            float4 v = *(const float4*)(xbf + r * 512 + col);
            cvt4(pC, (uint32_t)(r * 520 + col) * 2, v);
        }

        zacc<8>(acc);
        hg<128, 1, 2, 4, 520, false>(uC, aoffc, b0, b1, g_Bc2, 512, 0, 0, 8,
                                     boff72, wcpc, tid, acc);
        epi<1, 2, 4, false>(acc, s_b1, r0c, wcpc, lane,
            [&](int r, int c, float v) { store1(pA2, c * 40 + r, v); });

        zacc<8>(acc);
        load_b1<32, 32, 40>(pTB, g_B2a, 32, 0, tid);
        __syncthreads();
        mma1<2, 1, 2, 1, 40, 40, true>(uA2, uTB, aofft, boff40, 0, 0, 0, 0, acc);
        __syncthreads();
        epi<1, 2, 1, true>(acc, s_b2, r0t, 0, lane,
            [&](int r, int c, float v) { store1(pA3, r * 40 + c, v); });

        zacc<8>(acc);
        load_b1<32, 32, 40>(pTB, g_B2b, 32, 0, tid);
        __syncthreads();
        mma1<2, 1, 2, 1, 40, 40, true>(uA3, uTB, aofft, boff40, 0, 0, 0, 0, acc);
        float* ob = out + (long long)b * 28672 + 24576;
        epi<1, 2, 1, false>(acc, s_b3, r0t, 0, lane,
            [&](int r, int c, float v) { ob[c * 128 + r] = v; });
    }
}

// ---------------------------------------------------------------------------
extern "C" void kernel_launch(void* const* d_in, const int* in_sizes, int n_in,
                              void* d_out, int out_size) {
    const float* x   = (const float*)d_in[0];
    const float* lg  = (const float*)d_in[1];
    const float* lb  = (const float*)d_in[2];
    const float* W0a = (const float*)d_in[3];
    const float* b0a = (const float*)d_in[4];
    const float* W0b = (const float*)d_in[5];
    const float* b0b = (const float*)d_in[6];
    const float* c1w = (const float*)d_in[7];
    const float* c1b = (const float*)d_in[8];
    const float* W1a = (const float*)d_in[9];
    const float* b1a = (const float*)d_in[10];
    const float* W1b = (const float*)d_in[11];
    const float* b1b = (const float*)d_in[12];
    const float* c2w = (const float*)d_in[13];
    const float* c2b = (const float*)d_in[14];
    const float* W2a = (const float*)d_in[15];
    const float* b2a = (const float*)d_in[16];
    const float* W2b = (const float*)d_in[17];
    const float* b2b = (const float*)d_in[18];
    float* out = (float*)d_out;

    const int ds = 71680;
    cudaFuncSetAttribute(mega_kernel, cudaFuncAttributeMaxDynamicSharedMemorySize, ds);

    prep_k<<<128, 256>>>(W0a, W0b, W1a, W1b, W2a, W2b, c1w, c2w);
    mega_kernel<<<2048, 256, ds>>>(x, lg, lb, b0a, b0b, c1b, b1a, b1b,
                                   c2b, b2a, b2b, out);
}

// round 16
// speedup vs baseline: 1.9181x; 1.1210x over previous
#include <cuda_runtime.h>
#include <cuda_fp16.h>
#include <cstdint>

// MultiScaleTimeMixer: fused mega-kernel (1 batch/CTA, 3 phases).
// Pure fp16 1-pass MMA, fp32 acc. x pre-converted to fp16 (xh_k) so phases
// 1/2 stage A via raw cp.async. K=64 double-buffered weight chunks.
// 3 CTAs/SM (71680 B dsmem).

__device__ __align__(16) __half g_B0a[16384], g_B0b[16384];
__device__ __align__(16) __half g_B1a[4096],  g_B1b[4096];
__device__ __align__(16) __half g_B2a[1024],  g_B2b[1024];
__device__ __align__(16) __half g_Bc1[32768], g_Bc2[65536];
__device__ __align__(16) __half g_xh[(long long)2048 * 16384];
__device__ float g_mu[2048], g_rs[2048];

__device__ __forceinline__ uint32_t smem_u32(const void* p) {
    uint32_t a;
    asm("{ .reg .u64 t; cvta.to.shared.u64 t, %1; cvt.u32.u64 %0, t; }" : "=r"(a) : "l"(p));
    return a;
}
#define LDSM4(r, addr)                                                           \
    asm volatile("ldmatrix.sync.aligned.m8n8.x4.shared.b16 {%0,%1,%2,%3}, [%4];" \
        : "=r"((r)[0]), "=r"((r)[1]), "=r"((r)[2]), "=r"((r)[3]) : "r"(addr))
#define MMA16816(d, a, b0, b1)                                                   \
    asm volatile("mma.sync.aligned.m16n8k16.row.col.f32.f16.f16.f32 "            \
        "{%0,%1,%2,%3}, {%4,%5,%6,%7}, {%8,%9}, {%0,%1,%2,%3};"                  \
        : "+f"((d)[0]), "+f"((d)[1]), "+f"((d)[2]), "+f"((d)[3])                  \
        : "r"((a)[0]), "r"((a)[1]), "r"((a)[2]), "r"((a)[3]), "r"(b0), "r"(b1))
#define CP16(sa, g)                                                              \
    asm volatile("cp.async.cg.shared.global [%0], [%1], 16;" :: "r"(sa), "l"(g))
#define CP_COMMIT() asm volatile("cp.async.commit_group;" ::: "memory")
#define CP_WAIT1()  asm volatile("cp.async.wait_group 1;" ::: "memory")
#define CP_WAIT0()  asm volatile("cp.async.wait_group 0;" ::: "memory")

__device__ __forceinline__ uint32_t pack2h(__half a, __half b) {
    return (uint32_t)__half_as_ushort(a) | ((uint32_t)__half_as_ushort(b) << 16);
}
__device__ __forceinline__ float hswish(float v) {
    return v * fminf(fmaxf(v + 3.f, 0.f), 6.f) * (1.f / 6.f);
}
__device__ __forceinline__ void store1(char* p, int idx, float v) {
    *(__half*)(p + idx * 2) = __float2half_rn(v);
}

// ---------------- x -> fp16 copy + per-batch LN stats (one pass) ------------
__global__ void xh_k(const float* __restrict__ x) {
    int b = blockIdx.x;
    const float4* xp = (const float4*)(x + (long long)b * 16384);
    __half* xo = g_xh + (long long)b * 16384;
    float s = 0.f, q = 0.f;
    for (int i = threadIdx.x; i < 4096; i += 256) {
        float4 v = xp[i];
        s += v.x + v.y + v.z + v.w;
        q += v.x * v.x + v.y * v.y + v.z * v.z + v.w * v.w;
        uint2 u;
        u.x = pack2h(__float2half_rn(v.x), __float2half_rn(v.y));
        u.y = pack2h(__float2half_rn(v.z), __float2half_rn(v.w));
        *(uint2*)(xo + i * 4) = u;
    }
#pragma unroll
    for (int o = 16; o > 0; o >>= 1) {
        s += __shfl_down_sync(~0u, s, o); q += __shfl_down_sync(~0u, q, o);
    }
    __shared__ float ss[8], qs[8];
    int w = threadIdx.x >> 5, l = threadIdx.x & 31;
    if (l == 0) { ss[w] = s; qs[w] = q; }
    __syncthreads();
    if (threadIdx.x == 0) {
        float S = 0.f, Q = 0.f;
#pragma unroll
        for (int i = 0; i < 8; i++) { S += ss[i]; Q += qs[i]; }
        float mu = S * (1.f / 16384.f);
        g_mu[b] = mu;
        g_rs[b] = rsqrtf(Q * (1.f / 16384.f) - mu * mu + 1e-5f);
    }
}

__global__ void prep_k(const float* __restrict__ W0a, const float* __restrict__ W0b,
                       const float* __restrict__ W1a, const float* __restrict__ W1b,
                       const float* __restrict__ W2a, const float* __restrict__ W2b,
                       const float* __restrict__ c1w, const float* __restrict__ c2w) {
    int tid = blockIdx.x * blockDim.x + threadIdx.x, st = gridDim.x * blockDim.x;
    for (int i = tid; i < 16384; i += st) {
        int n = i >> 7, k = i & 127; float m = (k <= n) ? 1.f : 0.f;
        g_B0a[i] = __float2half_rn(m * W0a[i]);
        g_B0b[i] = __float2half_rn(m * W0b[i]);
    }
    for (int i = tid; i < 4096; i += st) {
        int n = i >> 6, k = i & 63; float m = (k <= n) ? 1.f : 0.f;
        g_B1a[i] = __float2half_rn(m * W1a[i]);
        g_B1b[i] = __float2half_rn(m * W1b[i]);
    }
    for (int i = tid; i < 1024; i += st) {
        int n = i >> 5, k = i & 31; float m = (k <= n) ? 1.f : 0.f;
        g_B2a[i] = __float2half_rn(m * W2a[i]);
        g_B2b[i] = __float2half_rn(m * W2b[i]);
    }
    for (int i = tid; i < 32768; i += st) {
        int co = i >> 8, k = i & 255;
        g_Bc1[i] = __float2half_rn(c1w[co * 256 + (k & 127) * 2 + (k >> 7)]);
    }
    for (int i = tid; i < 65536; i += st) {
        int co = i >> 9, k = i & 511;
        g_Bc2[i] = __float2half_rn(c2w[co * 512 + (k & 127) * 4 + (k >> 7)]);
    }
}

// sync-load a B tile (small triu GEMMs), single plane
template<int NROWS, int KCH, int SBH>
__device__ __forceinline__ void load_b1(char* pB, const __half* __restrict__ g,
    int ktot, int kbase, int tid) {
    constexpr int PER = KCH / 8, TOT = NROWS * PER;
    for (int i = tid; i < TOT; i += 256) {
        int n = i / PER, kq = i % PER;
        *(uint4*)(pB + (uint32_t)(n * SBH + kq * 8) * 2) =
            *(const uint4*)(g + n * ktot + kbase + kq * 8);
    }
}

// async-load one K=64 B chunk (stride 72 halves). local rows < nmin skipped.
template<int NR>
__device__ __forceinline__ void cpb64(uint32_t s, const __half* __restrict__ g,
    int ktot, int kbase, int rowbase, int nmin, int tid) {
    constexpr int TOT = NR * 8;
    for (int i = tid; i < TOT; i += 256) {
        int n = i >> 3, kq = i & 7;
        if (n < nmin) continue;
        CP16(s + (uint32_t)(n * 72 + kq * 8) * 2,
             g + (rowbase + n) * ktot + kbase + kq * 8);
    }
}

// 1-pass MMA over KS k16-steps. A (k-index ksA+kk local to A region);
// B chunk-local (stride SBH, index kk). TRI skip when global k16 (kg+kk)
// > global col group (gbase + gg).
template<int KS, int RB, int NG, int WC, int SAH, int SBH, bool TRI>
__device__ __forceinline__ void mma1(uint32_t uA, uint32_t uB,
    uint32_t aoff, uint32_t boff, int wcp, int ksA, int kg, int gbase,
    float (*acc)[4]) {
#pragma unroll
    for (int kk = 0; kk < KS; kk++) {
        int ka = ksA + kk, kt = kg + kk;
        uint32_t ah[RB][4];
        if (!TRI || kt <= gbase + (NG - 1) * WC + wcp) {
#pragma unroll
            for (int rb = 0; rb < RB; rb++)
                LDSM4(ah[rb], uA + aoff + rb * (16 * SAH * 2) + (uint32_t)ka * 32);
        }
#pragma unroll
        for (int g = 0; g < NG; g++) {
            int gg = g * WC + wcp;
            if (TRI && kt > gbase + gg) continue;
            uint32_t bh[4];
            LDSM4(bh, uB + boff + (uint32_t)(gg * (16 * SBH * 2) + kk * 32));
#pragma unroll
            for (int rb = 0; rb < RB; rb++) {
                MMA16816(acc[(rb * NG + g) * 2], ah[rb], bh[0], bh[1]);
                MMA16816(acc[(rb * NG + g) * 2 + 1], ah[rb], bh[2], bh[3]);
            }
        }
    }
}

// pipelined GEMM over global K=64 chunk range [c0,c1); A region local k
// starts at chunk c0. B rows [rowbase, rowbase+NR) with tril row pruning.
// Any cp.async groups committed BEFORE this call (e.g. A staging) complete
// by the first wait (groups retire in order).
template<int NR, int RB, int NG, int WC, int SAH, bool TRI>
__device__ __forceinline__ void hg(uint32_t uA, uint32_t aoff,
    uint32_t b0, uint32_t b1,
    const __half* __restrict__ g, int ktot, int rowbase, int c0, int c1,
    uint32_t boff, int wcp, int tid, float (*acc)[4]) {
    const int gbase = rowbase >> 4;
    cpb64<NR>(b0, g, ktot, c0 * 64, rowbase,
              TRI ? max(0, 64 * c0 - rowbase) : 0, tid);
    CP_COMMIT();
#pragma unroll 1
    for (int c = c0; c < c1; c++) {
        int idx = (c - c0) & 1;
        if (c + 1 < c1) {
            cpb64<NR>(idx ? b0 : b1, g, ktot, (c + 1) * 64, rowbase,
                      TRI ? max(0, 64 * (c + 1) - rowbase) : 0, tid);
            CP_COMMIT(); CP_WAIT1();
        } else CP_WAIT0();
        __syncthreads();
        mma1<4, RB, NG, WC, SAH, 72, TRI>(uA, idx ? b1 : b0, aoff, boff, wcp,
                                          (c - c0) * 4, c * 4, gbase, acc);
        __syncthreads();
    }
}

template<int NA> __device__ __forceinline__ void zacc(float (*acc)[4]) {
#pragma unroll
    for (int i = 0; i < NA; i++) { acc[i][0] = acc[i][1] = acc[i][2] = acc[i][3] = 0.f; }
}

template<int RB, int NG, int WC, bool HSW, class F>
__device__ __forceinline__ void epi(float (*acc)[4], const float* sb,
                                    int r0, int wcp, int lane, F f) {
#pragma unroll
    for (int rb = 0; rb < RB; rb++)
#pragma unroll
    for (int g = 0; g < NG; g++)
#pragma unroll
    for (int j = 0; j < 2; j++) {
        const float* a = acc[(rb * NG + g) * 2 + j];
        int cc = (g * WC + wcp) * 16 + j * 8 + 2 * (lane & 3);
        int r = r0 + rb * 16 + (lane >> 2);
        float b0 = sb[cc], b1 = sb[cc + 1];
        float v0 = a[0] + b0, v1 = a[1] + b1, v2 = a[2] + b0, v3 = a[3] + b1;
        if (HSW) { v0 = hswish(v0); v1 = hswish(v1); v2 = hswish(v2); v3 = hswish(v3); }
        f(r, cc, v0); f(r, cc + 1, v1); f(r + 8, cc, v2); f(r + 8, cc + 1, v3);
    }
}

// ---------------------------------------------------------------------------
// mega kernel: one CTA = one batch. dsmem = 71680 B, 3 CTAs/SM.
// ---------------------------------------------------------------------------
__global__ __launch_bounds__(256, 3)
void mega_kernel(const float* __restrict__ lg, const float* __restrict__ lb,
                 const float* __restrict__ b0a, const float* __restrict__ b0b,
                 const float* __restrict__ c1b, const float* __restrict__ b1a,
                 const float* __restrict__ b1b,
                 const float* __restrict__ c2b, const float* __restrict__ b2a,
                 const float* __restrict__ b2b,
                 float* __restrict__ out) {
    extern __shared__ char dsm[];
    __shared__ float s_b1[128], s_b2[128], s_b3[128];
    const int tid = threadIdx.x, lane = tid & 31, wid = tid >> 5;
    const int b = blockIdx.x;
    const uint32_t u0 = smem_u32(dsm);
    const __half* xh = g_xh + (long long)b * 16384;
    float acc[8][4];

    const int arow = ((lane >> 3) & 1) * 8 + (lane & 7);
    const int acol8 = (lane >> 4) * 8;
    const int brow = (lane >> 4) * 8 + (lane & 7);
    const int bcol8 = ((lane >> 3) & 1) * 8;
    const uint32_t boff72 = (uint32_t)(brow * 72 + bcol8) * 2;
    const uint32_t boff40 = (uint32_t)(brow * 40 + bcol8) * 2;

    //======================= phase 0: scale 0 ==============================
    // A (LN(xh) fp16) 128x136 at [0,34816); B bufs 64x72 at 34816 / 44032;
    // T2 128x72 at [53248,71680).
    // GEMM halves (N=64): GEMM1 half1 -> T2; GEMM1 half0 -> A cols 64..127;
    // GEMM2 reads T from those two regions.
    {
        const int r0 = (wid & 3) * 32, wcp = wid >> 2;
        char* pA = dsm;
        char* pT2 = dsm + 53248;
        const uint32_t uA = u0, uA1 = u0 + 128, uT2 = u0 + 53248;
        const uint32_t b0 = u0 + 34816, b1 = u0 + 44032;
        const uint32_t aoff = (uint32_t)((r0 + arow) * 136 + acol8) * 2;
        const uint32_t aoffT2 = (uint32_t)((r0 + arow) * 72 + acol8) * 2;
        if (tid < 128) { s_b1[tid] = b0a[tid]; s_b2[tid] = b0b[tid]; }
        const float mu = g_mu[b], rs = g_rs[b];

#pragma unroll
        for (int qq = 0; qq < 8; qq++) {
            int q = qq * 256 + tid;
            int r = q >> 4, col = (q & 15) * 8;
            uint4 hv = *(const uint4*)(xh + r * 128 + col);
            float4 g0 = *(const float4*)(lg + r * 128 + col);
            float4 g1 = *(const float4*)(lg + r * 128 + col + 4);
            float4 e0 = *(const float4*)(lb + r * 128 + col);
            float4 e1 = *(const float4*)(lb + r * 128 + col + 4);
            float2 f0 = __half22float2(*(__half2*)&hv.x);
            float2 f1 = __half22float2(*(__half2*)&hv.y);
            float2 f2 = __half22float2(*(__half2*)&hv.z);
            float2 f3 = __half22float2(*(__half2*)&hv.w);
            f0.x = (f0.x - mu) * rs * g0.x + e0.x; f0.y = (f0.y - mu) * rs * g0.y + e0.y;
            f1.x = (f1.x - mu) * rs * g0.z + e0.z; f1.y = (f1.y - mu) * rs * g0.w + e0.w;
            f2.x = (f2.x - mu) * rs * g1.x + e1.x; f2.y = (f2.y - mu) * rs * g1.y + e1.y;
            f3.x = (f3.x - mu) * rs * g1.z + e1.z; f3.y = (f3.y - mu) * rs * g1.w + e1.w;
            uint4 o;
            o.x = pack2h(__float2half_rn(f0.x), __float2half_rn(f0.y));
            o.y = pack2h(__float2half_rn(f1.x), __float2half_rn(f1.y));
            o.z = pack2h(__float2half_rn(f2.x), __float2half_rn(f2.y));
            o.w = pack2h(__float2half_rn(f3.x), __float2half_rn(f3.y));
            *(uint4*)(pA + (uint32_t)(r * 136 + col) * 2) = o;
        }

        // GEMM1 half1 (cols 64..127, full K=128) -> T2
        zacc<8>(acc);
        hg<64, 2, 2, 2, 136, true>(uA, aoff, b0, b1, g_B0a, 128, 64, 0, 2,
                                   boff72, wcp, tid, acc);
        epi<2, 2, 2, true>(acc, s_b1 + 64, r0, wcp, lane,
            [&](int r, int c, float v) { store1(pT2, r * 72 + c, v); });

        // GEMM1 half0 (cols 0..63, K<64) -> A cols 64..127 (dead region)
        zacc<8>(acc);
        hg<64, 2, 2, 2, 136, true>(uA, aoff, b0, b1, g_B0a, 128, 0, 0, 1,
                                   boff72, wcp, tid, acc);
        epi<2, 2, 2, true>(acc, s_b1, r0, wcp, lane,
            [&](int r, int c, float v) { store1(pA, r * 136 + 64 + c, v); });

        float* ob = out + (long long)b * 28672;
        // GEMM2 half1 (cols 64..127): K 0-63 from A region, 64-127 from T2
        zacc<8>(acc);
        hg<64, 2, 2, 2, 136, true>(uA1, aoff, b0, b1, g_B0b, 128, 64, 0, 1,
                                   boff72, wcp, tid, acc);
        hg<64, 2, 2, 2, 72, true>(uT2, aoffT2, b0, b1, g_B0b, 128, 64, 1, 2,
                                  boff72, wcp, tid, acc);
        epi<2, 2, 2, false>(acc, s_b2 + 64, r0, wcp, lane,
            [&](int r, int c, float v) { ob[(64 + c) * 128 + r] = v; });

        // GEMM2 half0 (cols 0..63, K<64)
        zacc<8>(acc);
        hg<64, 2, 2, 2, 136, true>(uA1, aoff, b0, b1, g_B0b, 128, 0, 0, 1,
                                   boff72, wcp, tid, acc);
        epi<2, 2, 2, false>(acc, s_b2, r0, wcp, lane,
            [&](int r, int c, float v) { ob[c * 128 + r] = v; });
    }

    //======================= phase 1: scale 1 ==============================
    // conv A 64x264 at [0,33792) staged via cp.async from xh;
    // B bufs 128x72 at 33792 / 52224 (end 70656).
    // post-conv: A2 128x72 [0,18432); A3 [18432,36864); triB [36864,46080).
    {
        __syncthreads();
        const int r0c = (wid & 1) * 32, wcpc = wid >> 1;
        const int r0t = (wid & 3) * 32, wcpt = wid >> 2;
        char* pA2 = dsm;          char* pA3 = dsm + 18432;
        char* pTB = dsm + 36864;
        const uint32_t uC = u0, uA2 = u0, uA3 = u0 + 18432;
        const uint32_t uTB = u0 + 36864;
        const uint32_t b0 = u0 + 33792, b1 = u0 + 52224;
        const uint32_t aoffc = (uint32_t)((r0c + arow) * 264 + acol8) * 2;
        const uint32_t aofft = (uint32_t)((r0t + arow) * 72 + acol8) * 2;
        if (tid < 128) s_b1[tid] = c1b[tid];
        if (tid < 64) { s_b2[tid] = b1a[tid]; s_b3[tid] = b1b[tid]; }

        // A staging: 64 rows x 256 halves contiguous (stride-2 conv reshape)
#pragma unroll
        for (int qq = 0; qq < 8; qq++) {
            int i = qq * 256 + tid;
            int r = i >> 5, kq = i & 31;
            CP16(uC + (uint32_t)(r * 264 + kq * 8) * 2, xh + r * 256 + kq * 8);
        }
        CP_COMMIT();

        zacc<8>(acc);
        hg<128, 2, 2, 4, 264, false>(uC, aoffc, b0, b1, g_Bc1, 256, 0, 0, 4,
                                     boff72, wcpc, tid, acc);
        epi<2, 2, 4, false>(acc, s_b1, r0c, wcpc, lane,
            [&](int r, int c, float v) { store1(pA2, c * 72 + r, v); });

        zacc<8>(acc);
        load_b1<64, 64, 72>(pTB, g_B1a, 64, 0, tid);
        __syncthreads();
        mma1<4, 2, 2, 2, 72, 72, true>(uA2, uTB, aofft, boff72, wcpt, 0, 0, 0, acc);
        __syncthreads();
        epi<2, 2, 2, true>(acc, s_b2, r0t, wcpt, lane,
            [&](int r, int c, float v) { store1(pA3, r * 72 + c, v); });

        zacc<8>(acc);
        load_b1<64, 64, 72>(pTB, g_B1b, 64, 0, tid);
        __syncthreads();
        mma1<4, 2, 2, 2, 72, 72, true>(uA3, uTB, aofft, boff72, wcpt, 0, 0, 0, acc);
        float* ob = out + (long long)b * 28672 + 16384;
        epi<2, 2, 2, false>(acc, s_b3, r0t, wcpt, lane,
            [&](int r, int c, float v) { ob[c * 128 + r] = v; });
    }

    //======================= phase 2: scale 2 ==============================
    // conv A 32x520 at [0,33280) staged via cp.async from xh;
    // B bufs 128x72 at 33280 / 51712 (end 70144).
    // post-conv: A2 128x40 [0,10240); A3 [10240,20480); triB [20480,23040).
    {
        __syncthreads();
        const int r0c = (wid & 1) * 16, wcpc = wid >> 1;
        const int r0t = wid * 16;
        char* pA2 = dsm;          char* pA3 = dsm + 10240;
        char* pTB = dsm + 20480;
        const uint32_t uC = u0, uA2 = u0, uA3 = u0 + 10240;
        const uint32_t uTB = u0 + 20480;
        const uint32_t b0 = u0 + 33280, b1 = u0 + 51712;
        const uint32_t aoffc = (uint32_t)((r0c + arow) * 520 + acol8) * 2;
        const uint32_t aofft = (uint32_t)((r0t + arow) * 40 + acol8) * 2;
        if (tid < 128) s_b1[tid] = c2b[tid];
        if (tid < 32) { s_b2[tid] = b2a[tid]; s_b3[tid] = b2b[tid]; }

        // A staging: 32 rows x 512 halves contiguous (stride-4 conv reshape)
#pragma unroll
        for (int qq = 0; qq < 8; qq++) {
            int i = qq * 256 + tid;
            int r = i >> 6, kq = i & 63;
            CP16(uC + (uint32_t)(r * 520 + kq * 8) * 2, xh + r * 512 + kq * 8);
        }
        CP_COMMIT();

        zacc<8>(acc);
        hg<128, 1, 2, 4, 520, false>(uC, aoffc, b0, b1, g_Bc2, 512, 0, 0, 8,
                                     boff72, wcpc, tid, acc);
        epi<1, 2, 4, false>(acc, s_b1, r0c, wcpc, lane,
            [&](int r, int c, float v) { store1(pA2, c * 40 + r, v); });

        zacc<8>(acc);
        load_b1<32, 32, 40>(pTB, g_B2a, 32, 0, tid);
        __syncthreads();
        mma1<2, 1, 2, 1, 40, 40, true>(uA2, uTB, aofft, boff40, 0, 0, 0, 0, acc);
        __syncthreads();
        epi<1, 2, 1, true>(acc, s_b2, r0t, 0, lane,
            [&](int r, int c, float v) { store1(pA3, r * 40 + c, v); });

        zacc<8>(acc);
        load_b1<32, 32, 40>(pTB, g_B2b, 32, 0, tid);
        __syncthreads();
        mma1<2, 1, 2, 1, 40, 40, true>(uA3, uTB, aofft, boff40, 0, 0, 0, 0, acc);
        float* ob = out + (long long)b * 28672 + 24576;
        epi<1, 2, 1, false>(acc, s_b3, r0t, 0, lane,
            [&](int r, int c, float v) { ob[c * 128 + r] = v; });
    }
}

// ---------------------------------------------------------------------------
extern "C" void kernel_launch(void* const* d_in, const int* in_sizes, int n_in,
                              void* d_out, int out_size) {
    const float* x   = (const float*)d_in[0];
    const float* lg  = (const float*)d_in[1];
    const float* lb  = (const float*)d_in[2];
    const float* W0a = (const float*)d_in[3];
    const float* b0a = (const float*)d_in[4];
    const float* W0b = (const float*)d_in[5];
    const float* b0b = (const float*)d_in[6];
    const float* c1w = (const float*)d_in[7];
    const float* c1b = (const float*)d_in[8];
    const float* W1a = (const float*)d_in[9];
    const float* b1a = (const float*)d_in[10];
    const float* W1b = (const float*)d_in[11];
    const float* b1b = (const float*)d_in[12];
    const float* c2w = (const float*)d_in[13];
    const float* c2b = (const float*)d_in[14];
    const float* W2a = (const float*)d_in[15];
    const float* b2a = (const float*)d_in[16];
    const float* W2b = (const float*)d_in[17];
    const float* b2b = (const float*)d_in[18];
    float* out = (float*)d_out;

    const int ds = 71680;
    cudaFuncSetAttribute(mega_kernel, cudaFuncAttributeMaxDynamicSharedMemorySize, ds);

    xh_k<<<2048, 256>>>(x);
    prep_k<<<128, 256>>>(W0a, W0b, W1a, W1b, W2a, W2b, c1w, c2w);
    mega_kernel<<<2048, 256, ds>>>(lg, lb, b0a, b0b, c1b, b1a, b1b,
                                   c2b, b2a, b2b, out);
}

// round 17
// speedup vs baseline: 1.9432x; 1.0131x over previous
#include <cuda_runtime.h>
#include <cuda_fp16.h>
#include <cstdint>

// MultiScaleTimeMixer: fused mega-kernel (1 batch/CTA, 3 phases).
// Pure fp16 1-pass MMA, fp32 acc. x pre-converted to fp16 (xh_k).
// K=64 double-buffered weight chunks, ONE sync per chunk; triu B tiles
// prefetched async under epilogues. 3 CTAs/SM (71680 B dsmem).

__device__ __align__(16) __half g_B0a[16384], g_B0b[16384];
__device__ __align__(16) __half g_B1a[4096],  g_B1b[4096];
__device__ __align__(16) __half g_B2a[1024],  g_B2b[1024];
__device__ __align__(16) __half g_Bc1[32768], g_Bc2[65536];
__device__ __align__(16) __half g_xh[(long long)2048 * 16384];
__device__ float g_mu[2048], g_rs[2048];

__device__ __forceinline__ uint32_t smem_u32(const void* p) {
    uint32_t a;
    asm("{ .reg .u64 t; cvta.to.shared.u64 t, %1; cvt.u32.u64 %0, t; }" : "=r"(a) : "l"(p));
    return a;
}
#define LDSM4(r, addr)                                                           \
    asm volatile("ldmatrix.sync.aligned.m8n8.x4.shared.b16 {%0,%1,%2,%3}, [%4];" \
        : "=r"((r)[0]), "=r"((r)[1]), "=r"((r)[2]), "=r"((r)[3]) : "r"(addr))
#define MMA16816(d, a, b0, b1)                                                   \
    asm volatile("mma.sync.aligned.m16n8k16.row.col.f32.f16.f16.f32 "            \
        "{%0,%1,%2,%3}, {%4,%5,%6,%7}, {%8,%9}, {%0,%1,%2,%3};"                  \
        : "+f"((d)[0]), "+f"((d)[1]), "+f"((d)[2]), "+f"((d)[3])                  \
        : "r"((a)[0]), "r"((a)[1]), "r"((a)[2]), "r"((a)[3]), "r"(b0), "r"(b1))
#define CP16(sa, g)                                                              \
    asm volatile("cp.async.cg.shared.global [%0], [%1], 16;" :: "r"(sa), "l"(g))
#define CP_COMMIT() asm volatile("cp.async.commit_group;" ::: "memory")
#define CP_WAIT0()  asm volatile("cp.async.wait_group 0;" ::: "memory")

__device__ __forceinline__ uint32_t pack2h(__half a, __half b) {
    return (uint32_t)__half_as_ushort(a) | ((uint32_t)__half_as_ushort(b) << 16);
}
__device__ __forceinline__ float hswish(float v) {
    return v * fminf(fmaxf(v + 3.f, 0.f), 6.f) * (1.f / 6.f);
}
__device__ __forceinline__ void store1(char* p, int idx, float v) {
    *(__half*)(p + idx * 2) = __float2half_rn(v);
}

// ---------------- x -> fp16 copy + per-batch LN stats (one pass) ------------
__global__ void xh_k(const float* __restrict__ x) {
    int b = blockIdx.x;
    const float4* xp = (const float4*)(x + (long long)b * 16384);
    __half* xo = g_xh + (long long)b * 16384;
    float s = 0.f, q = 0.f;
    for (int i = threadIdx.x; i < 4096; i += 256) {
        float4 v = xp[i];
        s += v.x + v.y + v.z + v.w;
        q += v.x * v.x + v.y * v.y + v.z * v.z + v.w * v.w;
        uint2 u;
        u.x = pack2h(__float2half_rn(v.x), __float2half_rn(v.y));
        u.y = pack2h(__float2half_rn(v.z), __float2half_rn(v.w));
        *(uint2*)(xo + i * 4) = u;
    }
#pragma unroll
    for (int o = 16; o > 0; o >>= 1) {
        s += __shfl_down_sync(~0u, s, o); q += __shfl_down_sync(~0u, q, o);
    }
    __shared__ float ss[8], qs[8];
    int w = threadIdx.x >> 5, l = threadIdx.x & 31;
    if (l == 0) { ss[w] = s; qs[w] = q; }
    __syncthreads();
    if (threadIdx.x == 0) {
        float S = 0.f, Q = 0.f;
#pragma unroll
        for (int i = 0; i < 8; i++) { S += ss[i]; Q += qs[i]; }
        float mu = S * (1.f / 16384.f);
        g_mu[b] = mu;
        g_rs[b] = rsqrtf(Q * (1.f / 16384.f) - mu * mu + 1e-5f);
    }
}

__global__ void prep_k(const float* __restrict__ W0a, const float* __restrict__ W0b,
                       const float* __restrict__ W1a, const float* __restrict__ W1b,
                       const float* __restrict__ W2a, const float* __restrict__ W2b,
                       const float* __restrict__ c1w, const float* __restrict__ c2w) {
    int tid = blockIdx.x * blockDim.x + threadIdx.x, st = gridDim.x * blockDim.x;
    for (int i = tid; i < 16384; i += st) {
        int n = i >> 7, k = i & 127; float m = (k <= n) ? 1.f : 0.f;
        g_B0a[i] = __float2half_rn(m * W0a[i]);
        g_B0b[i] = __float2half_rn(m * W0b[i]);
    }
    for (int i = tid; i < 4096; i += st) {
        int n = i >> 6, k = i & 63; float m = (k <= n) ? 1.f : 0.f;
        g_B1a[i] = __float2half_rn(m * W1a[i]);
        g_B1b[i] = __float2half_rn(m * W1b[i]);
    }
    for (int i = tid; i < 1024; i += st) {
        int n = i >> 5, k = i & 31; float m = (k <= n) ? 1.f : 0.f;
        g_B2a[i] = __float2half_rn(m * W2a[i]);
        g_B2b[i] = __float2half_rn(m * W2b[i]);
    }
    for (int i = tid; i < 32768; i += st) {
        int co = i >> 8, k = i & 255;
        g_Bc1[i] = __float2half_rn(c1w[co * 256 + (k & 127) * 2 + (k >> 7)]);
    }
    for (int i = tid; i < 65536; i += st) {
        int co = i >> 9, k = i & 511;
        g_Bc2[i] = __float2half_rn(c2w[co * 512 + (k & 127) * 4 + (k >> 7)]);
    }
}

// async-load a B tile (triu GEMMs), single plane
template<int NROWS, int KCH, int SBH>
__device__ __forceinline__ void cp_b1(uint32_t s, const __half* __restrict__ g,
    int ktot, int kbase, int tid) {
    constexpr int PER = KCH / 8, TOT = NROWS * PER;
    for (int i = tid; i < TOT; i += 256) {
        int n = i / PER, kq = i % PER;
        CP16(s + (uint32_t)(n * SBH + kq * 8) * 2, g + n * ktot + kbase + kq * 8);
    }
}

// async-load one K=64 B chunk (stride 72 halves). local rows < nmin skipped.
template<int NR>
__device__ __forceinline__ void cpb64(uint32_t s, const __half* __restrict__ g,
    int ktot, int kbase, int rowbase, int nmin, int tid) {
    constexpr int TOT = NR * 8;
    for (int i = tid; i < TOT; i += 256) {
        int n = i >> 3, kq = i & 7;
        if (n < nmin) continue;
        CP16(s + (uint32_t)(n * 72 + kq * 8) * 2,
             g + (rowbase + n) * ktot + kbase + kq * 8);
    }
}

// 1-pass MMA over KS k16-steps. A (k-index ksA+kk local to A region);
// B chunk-local (stride SBH, index kk). TRI skip when global k16 (kg+kk)
// > global col group (gbase + gg).
template<int KS, int RB, int NG, int WC, int SAH, int SBH, bool TRI>
__device__ __forceinline__ void mma1(uint32_t uA, uint32_t uB,
    uint32_t aoff, uint32_t boff, int wcp, int ksA, int kg, int gbase,
    float (*acc)[4]) {
#pragma unroll
    for (int kk = 0; kk < KS; kk++) {
        int ka = ksA + kk, kt = kg + kk;
        uint32_t ah[RB][4];
        if (!TRI || kt <= gbase + (NG - 1) * WC + wcp) {
#pragma unroll
            for (int rb = 0; rb < RB; rb++)
                LDSM4(ah[rb], uA + aoff + rb * (16 * SAH * 2) + (uint32_t)ka * 32);
        }
#pragma unroll
        for (int g = 0; g < NG; g++) {
            int gg = g * WC + wcp;
            if (TRI && kt > gbase + gg) continue;
            uint32_t bh[4];
            LDSM4(bh, uB + boff + (uint32_t)(gg * (16 * SBH * 2) + kk * 32));
#pragma unroll
            for (int rb = 0; rb < RB; rb++) {
                MMA16816(acc[(rb * NG + g) * 2], ah[rb], bh[0], bh[1]);
                MMA16816(acc[(rb * NG + g) * 2 + 1], ah[rb], bh[2], bh[3]);
            }
        }
    }
}

// pipelined GEMM over global K=64 chunk range [c0,c1), ONE sync per chunk:
//   wait(chunk c) ; sync ; prefetch(chunk c+1) ; mma(chunk c)
// The sync proves chunk c visible AND all warps done reading the buffer that
// prefetch overwrites (consumed in iteration c-1). Trailing sync protects
// buffers/epilogue regions for the caller. Pre-committed cp groups (A
// staging) retire at the first wait.
template<int NR, int RB, int NG, int WC, int SAH, bool TRI>
__device__ __forceinline__ void hg(uint32_t uA, uint32_t aoff,
    uint32_t b0, uint32_t b1,
    const __half* __restrict__ g, int ktot, int rowbase, int c0, int c1,
    uint32_t boff, int wcp, int tid, float (*acc)[4]) {
    const int gbase = rowbase >> 4;
    cpb64<NR>(b0, g, ktot, c0 * 64, rowbase,
              TRI ? max(0, 64 * c0 - rowbase) : 0, tid);
    CP_COMMIT();
#pragma unroll 1
    for (int c = c0; c < c1; c++) {
        int idx = (c - c0) & 1;
        CP_WAIT0();
        __syncthreads();
        if (c + 1 < c1) {
            cpb64<NR>(idx ? b0 : b1, g, ktot, (c + 1) * 64, rowbase,
                      TRI ? max(0, 64 * (c + 1) - rowbase) : 0, tid);
            CP_COMMIT();
        }
        mma1<4, RB, NG, WC, SAH, 72, TRI>(uA, idx ? b1 : b0, aoff, boff, wcp,
                                          (c - c0) * 4, c * 4, gbase, acc);
    }
    __syncthreads();
}

template<int NA> __device__ __forceinline__ void zacc(float (*acc)[4]) {
#pragma unroll
    for (int i = 0; i < NA; i++) { acc[i][0] = acc[i][1] = acc[i][2] = acc[i][3] = 0.f; }
}

template<int RB, int NG, int WC, bool HSW, class F>
__device__ __forceinline__ void epi(float (*acc)[4], const float* sb,
                                    int r0, int wcp, int lane, F f) {
#pragma unroll
    for (int rb = 0; rb < RB; rb++)
#pragma unroll
    for (int g = 0; g < NG; g++)
#pragma unroll
    for (int j = 0; j < 2; j++) {
        const float* a = acc[(rb * NG + g) * 2 + j];
        int cc = (g * WC + wcp) * 16 + j * 8 + 2 * (lane & 3);
        int r = r0 + rb * 16 + (lane >> 2);
        float b0 = sb[cc], b1 = sb[cc + 1];
        float v0 = a[0] + b0, v1 = a[1] + b1, v2 = a[2] + b0, v3 = a[3] + b1;
        if (HSW) { v0 = hswish(v0); v1 = hswish(v1); v2 = hswish(v2); v3 = hswish(v3); }
        f(r, cc, v0); f(r, cc + 1, v1); f(r + 8, cc, v2); f(r + 8, cc + 1, v3);
    }
}

// ---------------------------------------------------------------------------
// mega kernel: one CTA = one batch. dsmem = 71680 B, 3 CTAs/SM.
// ---------------------------------------------------------------------------
__global__ __launch_bounds__(256, 3)
void mega_kernel(const float* __restrict__ lg, const float* __restrict__ lb,
                 const float* __restrict__ b0a, const float* __restrict__ b0b,
                 const float* __restrict__ c1b, const float* __restrict__ b1a,
                 const float* __restrict__ b1b,
                 const float* __restrict__ c2b, const float* __restrict__ b2a,
                 const float* __restrict__ b2b,
                 float* __restrict__ out) {
    extern __shared__ char dsm[];
    __shared__ float s_b1[128], s_b2[128], s_b3[128];
    const int tid = threadIdx.x, lane = tid & 31, wid = tid >> 5;
    const int b = blockIdx.x;
    const uint32_t u0 = smem_u32(dsm);
    const __half* xh = g_xh + (long long)b * 16384;
    float acc[8][4];

    const int arow = ((lane >> 3) & 1) * 8 + (lane & 7);
    const int acol8 = (lane >> 4) * 8;
    const int brow = (lane >> 4) * 8 + (lane & 7);
    const int bcol8 = ((lane >> 3) & 1) * 8;
    const uint32_t boff72 = (uint32_t)(brow * 72 + bcol8) * 2;
    const uint32_t boff40 = (uint32_t)(brow * 40 + bcol8) * 2;

    //======================= phase 0: scale 0 ==============================
    // A (LN(xh) fp16) 128x136 at [0,34816); B bufs 64x72 at 34816 / 44032;
    // T2 128x72 at [53248,71680).
    // GEMM halves (N=64): GEMM1 half1 -> T2; GEMM1 half0 -> A cols 64..127;
    // GEMM2 reads T from those two regions.
    {
        const int r0 = (wid & 3) * 32, wcp = wid >> 2;
        char* pA = dsm;
        char* pT2 = dsm + 53248;
        const uint32_t uA = u0, uA1 = u0 + 128, uT2 = u0 + 53248;
        const uint32_t b0 = u0 + 34816, b1 = u0 + 44032;
        const uint32_t aoff = (uint32_t)((r0 + arow) * 136 + acol8) * 2;
        const uint32_t aoffT2 = (uint32_t)((r0 + arow) * 72 + acol8) * 2;
        if (tid < 128) { s_b1[tid] = b0a[tid]; s_b2[tid] = b0b[tid]; }
        const float mu = g_mu[b], rs = g_rs[b];

#pragma unroll
        for (int qq = 0; qq < 8; qq++) {
            int q = qq * 256 + tid;
            int r = q >> 4, col = (q & 15) * 8;
            uint4 hv = *(const uint4*)(xh + r * 128 + col);
            float4 g0 = *(const float4*)(lg + r * 128 + col);
            float4 g1 = *(const float4*)(lg + r * 128 + col + 4);
            float4 e0 = *(const float4*)(lb + r * 128 + col);
            float4 e1 = *(const float4*)(lb + r * 128 + col + 4);
            float2 f0 = __half22float2(*(__half2*)&hv.x);
            float2 f1 = __half22float2(*(__half2*)&hv.y);
            float2 f2 = __half22float2(*(__half2*)&hv.z);
            float2 f3 = __half22float2(*(__half2*)&hv.w);
            f0.x = (f0.x - mu) * rs * g0.x + e0.x; f0.y = (f0.y - mu) * rs * g0.y + e0.y;
            f1.x = (f1.x - mu) * rs * g0.z + e0.z; f1.y = (f1.y - mu) * rs * g0.w + e0.w;
            f2.x = (f2.x - mu) * rs * g1.x + e1.x; f2.y = (f2.y - mu) * rs * g1.y + e1.y;
            f3.x = (f3.x - mu) * rs * g1.z + e1.z; f3.y = (f3.y - mu) * rs * g1.w + e1.w;
            uint4 o;
            o.x = pack2h(__float2half_rn(f0.x), __float2half_rn(f0.y));
            o.y = pack2h(__float2half_rn(f1.x), __float2half_rn(f1.y));
            o.z = pack2h(__float2half_rn(f2.x), __float2half_rn(f2.y));
            o.w = pack2h(__float2half_rn(f3.x), __float2half_rn(f3.y));
            *(uint4*)(pA + (uint32_t)(r * 136 + col) * 2) = o;
        }

        // GEMM1 half1 (cols 64..127, full K=128) -> T2
        zacc<8>(acc);
        hg<64, 2, 2, 2, 136, true>(uA, aoff, b0, b1, g_B0a, 128, 64, 0, 2,
                                   boff72, wcp, tid, acc);
        epi<2, 2, 2, true>(acc, s_b1 + 64, r0, wcp, lane,
            [&](int r, int c, float v) { store1(pT2, r * 72 + c, v); });

        // GEMM1 half0 (cols 0..63, K<64) -> A cols 64..127 (dead region)
        zacc<8>(acc);
        hg<64, 2, 2, 2, 136, true>(uA, aoff, b0, b1, g_B0a, 128, 0, 0, 1,
                                   boff72, wcp, tid, acc);
        epi<2, 2, 2, true>(acc, s_b1, r0, wcp, lane,
            [&](int r, int c, float v) { store1(pA, r * 136 + 64 + c, v); });

        float* ob = out + (long long)b * 28672;
        // GEMM2 half1 (cols 64..127): K 0-63 from A region, 64-127 from T2
        zacc<8>(acc);
        hg<64, 2, 2, 2, 136, true>(uA1, aoff, b0, b1, g_B0b, 128, 64, 0, 1,
                                   boff72, wcp, tid, acc);
        hg<64, 2, 2, 2, 72, true>(uT2, aoffT2, b0, b1, g_B0b, 128, 64, 1, 2,
                                  boff72, wcp, tid, acc);
        epi<2, 2, 2, false>(acc, s_b2 + 64, r0, wcp, lane,
            [&](int r, int c, float v) { ob[(64 + c) * 128 + r] = v; });

        // GEMM2 half0 (cols 0..63, K<64)
        zacc<8>(acc);
        hg<64, 2, 2, 2, 136, true>(uA1, aoff, b0, b1, g_B0b, 128, 0, 0, 1,
                                   boff72, wcp, tid, acc);
        epi<2, 2, 2, false>(acc, s_b2, r0, wcp, lane,
            [&](int r, int c, float v) { ob[c * 128 + r] = v; });
    }

    //======================= phase 1: scale 1 ==============================
    // conv A 64x264 at [0,33792) staged via cp.async from xh;
    // B bufs 128x72 at 33792 / 52224 (end 70656).
    // post-conv: A2 128x72 [0,18432); A3 [18432,36864); triB [36864,46080)
    // (aliases dead b0; all conv readers past hg's trailing sync).
    {
        __syncthreads();
        const int r0c = (wid & 1) * 32, wcpc = wid >> 1;
        const int r0t = (wid & 3) * 32, wcpt = wid >> 2;
        char* pA2 = dsm;          char* pA3 = dsm + 18432;
        const uint32_t uC = u0, uA2 = u0, uA3 = u0 + 18432;
        const uint32_t uTB = u0 + 36864;
        const uint32_t b0 = u0 + 33792, b1 = u0 + 52224;
        const uint32_t aoffc = (uint32_t)((r0c + arow) * 264 + acol8) * 2;
        const uint32_t aofft = (uint32_t)((r0t + arow) * 72 + acol8) * 2;
        if (tid < 128) s_b1[tid] = c1b[tid];
        if (tid < 64) { s_b2[tid] = b1a[tid]; s_b3[tid] = b1b[tid]; }

        // A staging: 64 rows x 256 halves contiguous (stride-2 conv reshape)
#pragma unroll
        for (int qq = 0; qq < 8; qq++) {
            int i = qq * 256 + tid;
            int r = i >> 5, kq = i & 31;
            CP16(uC + (uint32_t)(r * 264 + kq * 8) * 2, xh + r * 256 + kq * 8);
        }
        CP_COMMIT();

        zacc<8>(acc);
        hg<128, 2, 2, 4, 264, false>(uC, aoffc, b0, b1, g_Bc1, 256, 0, 0, 4,
                                     boff72, wcpc, tid, acc);
        // prefetch triB under conv epilogue
        cp_b1<64, 64, 72>(uTB, g_B1a, 64, 0, tid);
        CP_COMMIT();
        epi<2, 2, 4, false>(acc, s_b1, r0c, wcpc, lane,
            [&](int r, int c, float v) { store1(pA2, c * 72 + r, v); });

        zacc<8>(acc);
        CP_WAIT0();
        __syncthreads();
        mma1<4, 2, 2, 2, 72, 72, true>(uA2, uTB, aofft, boff72, wcpt, 0, 0, 0, acc);
        __syncthreads();
        cp_b1<64, 64, 72>(uTB, g_B1b, 64, 0, tid);
        CP_COMMIT();
        epi<2, 2, 2, true>(acc, s_b2, r0t, wcpt, lane,
            [&](int r, int c, float v) { store1(pA3, r * 72 + c, v); });

        zacc<8>(acc);
        CP_WAIT0();
        __syncthreads();
        mma1<4, 2, 2, 2, 72, 72, true>(uA3, uTB, aofft, boff72, wcpt, 0, 0, 0, acc);
        float* ob = out + (long long)b * 28672 + 16384;
        epi<2, 2, 2, false>(acc, s_b3, r0t, wcpt, lane,
            [&](int r, int c, float v) { ob[c * 128 + r] = v; });
    }

    //======================= phase 2: scale 2 ==============================
    // conv A 32x520 at [0,33280) staged via cp.async from xh;
    // B bufs 128x72 at 33280 / 51712 (end 70144).
    // post-conv: A2 128x40 [0,10240); A3 [10240,20480); triB [20480,23040)
    // (inside dead conv-A region; all conv readers past trailing sync).
    {
        __syncthreads();
        const int r0c = (wid & 1) * 16, wcpc = wid >> 1;
        const int r0t = wid * 16;
        char* pA2 = dsm;          char* pA3 = dsm + 10240;
        const uint32_t uC = u0, uA2 = u0, uA3 = u0 + 10240;
        const uint32_t uTB = u0 + 20480;
        const uint32_t b0 = u0 + 33280, b1 = u0 + 51712;
        const uint32_t aoffc = (uint32_t)((r0c + arow) * 520 + acol8) * 2;
        const uint32_t aofft = (uint32_t)((r0t + arow) * 40 + acol8) * 2;
        if (tid < 128) s_b1[tid] = c2b[tid];
        if (tid < 32) { s_b2[tid] = b2a[tid]; s_b3[tid] = b2b[tid]; }

        // A staging: 32 rows x 512 halves contiguous (stride-4 conv reshape)
#pragma unroll
        for (int qq = 0; qq < 8; qq++) {
            int i = qq * 256 + tid;
            int r = i >> 6, kq = i & 63;
            CP16(uC + (uint32_t)(r * 520 + kq * 8) * 2, xh + r * 512 + kq * 8);
        }
        CP_COMMIT();

        zacc<8>(acc);
        hg<128, 1, 2, 4, 520, false>(uC, aoffc, b0, b1, g_Bc2, 512, 0, 0, 8,
                                     boff72, wcpc, tid, acc);
        cp_b1<32, 32, 40>(uTB, g_B2a, 32, 0, tid);
        CP_COMMIT();
        epi<1, 2, 4, false>(acc, s_b1, r0c, wcpc, lane,
            [&](int r, int c, float v) { store1(pA2, c * 40 + r, v); });

        zacc<8>(acc);
        CP_WAIT0();
        __syncthreads();
        mma1<2, 1, 2, 1, 40, 40, true>(uA2, uTB, aofft, boff40, 0, 0, 0, 0, acc);
        __syncthreads();
        cp_b1<32, 32, 40>(uTB, g_B2b, 32, 0, tid);
        CP_COMMIT();
        epi<1, 2, 1, true>(acc, s_b2, r0t, 0, lane,
            [&](int r, int c, float v) { store1(pA3, r * 40 + c, v); });

        zacc<8>(acc);
        CP_WAIT0();
        __syncthreads();
        mma1<2, 1, 2, 1, 40, 40, true>(uA3, uTB, aofft, boff40, 0, 0, 0, 0, acc);
        float* ob = out + (long long)b * 28672 + 24576;
        epi<1, 2, 1, false>(acc, s_b3, r0t, 0, lane,
            [&](int r, int c, float v) { ob[c * 128 + r] = v; });
    }
}

// ---------------------------------------------------------------------------
extern "C" void kernel_launch(void* const* d_in, const int* in_sizes, int n_in,
                              void* d_out, int out_size) {
    const float* x   = (const float*)d_in[0];
    const float* lg  = (const float*)d_in[1];
    const float* lb  = (const float*)d_in[2];
    const float* W0a = (const float*)d_in[3];
    const float* b0a = (const float*)d_in[4];
    const float* W0b = (const float*)d_in[5];
    const float* b0b = (const float*)d_in[6];
    const float* c1w = (const float*)d_in[7];
    const float* c1b = (const float*)d_in[8];
    const float* W1a = (const float*)d_in[9];
    const float* b1a = (const float*)d_in[10];
    const float* W1b = (const float*)d_in[11];
    const float* b1b = (const float*)d_in[12];
    const float* c2w = (const float*)d_in[13];
    const float* c2b = (const float*)d_in[14];
    const float* W2a = (const float*)d_in[15];
    const float* b2a = (const float*)d_in[16];
    const float* W2b = (const float*)d_in[17];
    const float* b2b = (const float*)d_in[18];
    float* out = (float*)d_out;

    const int ds = 71680;
    cudaFuncSetAttribute(mega_kernel, cudaFuncAttributeMaxDynamicSharedMemorySize, ds);

    xh_k<<<2048, 256>>>(x);
    prep_k<<<128, 256>>>(W0a, W0b, W1a, W1b, W2a, W2b, c1w, c2w);
    mega_kernel<<<2048, 256, ds>>>(lg, lb, b0a, b0b, c1b, b1a, b1b,
                                   c2b, b2a, b2b, out);
}